// round 6
// baseline (speedup 1.0000x reference)
#include <cuda_runtime.h>
#include <cuda_bf16.h>
#include <math.h>
#include <stdint.h>

#define BATCH 4
#define TLEN  4096
#define EDIM  1024
#define DDIM  128
#define MTOT  (BATCH*TLEN)
typedef __nv_bfloat16 bf16;

// q pre-scale: 1/sqrt(128) * log2(e)
#define QSCALE ((float)(0.08838834764831843 * 1.4426950408889634))

// ---------------- device scratch ----------------
__device__ bf16 g_xh[(size_t)MTOT*EDIM];
__device__ bf16 g_xl[(size_t)MTOT*EDIM];
__device__ bf16 g_wth[3*DDIM*EDIM];
__device__ bf16 g_wtl[3*DDIM*EDIM];
__device__ bf16 g_wpth[DDIM*DDIM];
__device__ bf16 g_wptl[DDIM*DDIM];
__device__ bf16 g_qh[(size_t)MTOT*DDIM], g_ql[(size_t)MTOT*DDIM];
__device__ bf16 g_kh[(size_t)MTOT*DDIM], g_kl[(size_t)MTOT*DDIM];
__device__ bf16 g_vh[(size_t)MTOT*DDIM], g_vl[(size_t)MTOT*DDIM];
__device__ bf16 g_oh[(size_t)MTOT*DDIM], g_ol[(size_t)MTOT*DDIM];
__device__ unsigned int g_ctr;

// ---------------- helpers ----------------
__device__ __forceinline__ uint32_t su32(const void* p) {
    return (uint32_t)__cvta_generic_to_shared(p);
}
__device__ __forceinline__ void cp16(uint32_t dst, const void* src) {
    asm volatile("cp.async.cg.shared.global [%0], [%1], 16;" :: "r"(dst), "l"(src));
}
#define CP_COMMIT() asm volatile("cp.async.commit_group;" ::: "memory")
template<int N> __device__ __forceinline__ void cp_wait() {
    asm volatile("cp.async.wait_group %0;" :: "n"(N) : "memory");
}
__device__ __forceinline__ uint32_t swz(uint32_t off) {       // 128B rows
    return off ^ ((off >> 3) & 0x70);
}
__device__ __forceinline__ uint32_t sw256(int r, int cb) {    // 256B rows
    return (uint32_t)(r * 256 + (cb ^ ((r & 7) << 4)));
}
#define LDSM4(r, addr) \
    asm volatile("ldmatrix.sync.aligned.m8n8.x4.shared.b16 {%0,%1,%2,%3}, [%4];" \
        : "=r"((r)[0]), "=r"((r)[1]), "=r"((r)[2]), "=r"((r)[3]) : "r"(addr))
#define LDSM4T(r, addr) \
    asm volatile("ldmatrix.sync.aligned.m8n8.x4.trans.shared.b16 {%0,%1,%2,%3}, [%4];" \
        : "=r"((r)[0]), "=r"((r)[1]), "=r"((r)[2]), "=r"((r)[3]) : "r"(addr))
#define MMA16816(d, a, b0, b1) \
    asm volatile("mma.sync.aligned.m16n8k16.row.col.f32.bf16.bf16.f32 " \
        "{%0,%1,%2,%3}, {%4,%5,%6,%7}, {%8,%9}, {%0,%1,%2,%3};" \
        : "+f"((d)[0]), "+f"((d)[1]), "+f"((d)[2]), "+f"((d)[3]) \
        : "r"((a)[0]), "r"((a)[1]), "r"((a)[2]), "r"((a)[3]), "r"(b0), "r"(b1))

__device__ __forceinline__ uint32_t pk2(float lo, float hi) { // {low:lo, high:hi}
    uint32_t r;
    asm("cvt.rn.bf16x2.f32 %0, %1, %2;" : "=r"(r) : "f"(hi), "f"(lo));
    return r;
}
__device__ __forceinline__ float lo_f(uint32_t h) { return __uint_as_float(h << 16); }
__device__ __forceinline__ float hi_f(uint32_t h) { return __uint_as_float(h & 0xffff0000u); }
__device__ __forceinline__ float ex2(float x) {
    float y; asm("ex2.approx.f32 %0, %1;" : "=f"(y) : "f"(x)); return y;
}

// ---------------- split fp32 -> bf16 hi/lo ----------------
__global__ __launch_bounds__(256) void split_f32(const float* __restrict__ s,
                                                 bf16* __restrict__ h,
                                                 bf16* __restrict__ l, int n4) {
    int idx = blockIdx.x * 256 + threadIdx.x;
    if (idx >= n4) return;
    float4 v = ((const float4*)s)[idx];
    float vv[4] = {v.x, v.y, v.z, v.w};
    uint32_t h0 = pk2(vv[0], vv[1]), h1 = pk2(vv[2], vv[3]);
    uint32_t l0 = pk2(vv[0] - lo_f(h0), vv[1] - hi_f(h0));
    uint32_t l1 = pk2(vv[2] - lo_f(h1), vv[3] - hi_f(h1));
    ((uint32_t*)h)[idx*2] = h0; ((uint32_t*)h)[idx*2+1] = h1;
    ((uint32_t*)l)[idx*2] = l0; ((uint32_t*)l)[idx*2+1] = l1;
}

// ---------------- transpose + split weights ----------------
__global__ __launch_bounds__(256) void convert_w(
    const float* __restrict__ wq, const float* __restrict__ wk,
    const float* __restrict__ wv, const float* __restrict__ wp,
    bf16* __restrict__ wth, bf16* __restrict__ wtl,
    bf16* __restrict__ wpth, bf16* __restrict__ wptl) {
    int idx = blockIdx.x * 256 + threadIdx.x;
    if (idx < 3 * DDIM * EDIM) {
        int k = idx & (EDIM - 1), n = (idx >> 10) & (DDIM - 1), w = idx >> 17;
        const float* W = (w == 0) ? wq : ((w == 1) ? wk : wv);
        float v = W[(size_t)k * DDIM + n];
        bf16 h = __float2bfloat16(v);
        wth[idx] = h; wtl[idx] = __float2bfloat16(v - __bfloat162float(h));
    }
    if (idx < DDIM * DDIM) {
        int k = idx & 127, n = idx >> 7;
        float v = wp[(size_t)k * DDIM + n];
        bf16 h = __float2bfloat16(v);
        wpth[idx] = h; wptl[idx] = __float2bfloat16(v - __bfloat162float(h));
    }
}

// ---------------------------------------------------------------------------
// C[M,128] = A[M,K] @ Bt[128,K]^T, split bf16, 3-pass, double-buffered.
// BM=64, BN=128, 256 threads (8 warps: 2m x 4n), 48KB/stage x2 = 96KB,
// 2 CTAs/SM. SPLIT=1: write bf16 hi/lo w/ scale; SPLIT=0: write fp32.
// ---------------------------------------------------------------------------
template<int SPLIT>
__global__ __launch_bounds__(256, 2) void mm_bf16(
    const bf16* __restrict__ Ah, const bf16* __restrict__ Al,
    const bf16* __restrict__ Bh, const bf16* __restrict__ Bl,
    float* __restrict__ C, bf16* __restrict__ Ch, bf16* __restrict__ Cl,
    float oscale, int K) {
    extern __shared__ char smem[];
    const uint32_t sb = su32(smem);
    const int tid = threadIdx.x, lane = tid & 31, warp = tid >> 5;
    const int wm = (warp & 1) * 32, wn = (warp >> 1) * 32;
    const int m0 = blockIdx.x * 64;

    float acc[2][4][4];
#pragma unroll
    for (int i = 0; i < 2; i++)
#pragma unroll
        for (int j = 0; j < 4; j++)
#pragma unroll
            for (int u = 0; u < 4; u++) acc[i][j][u] = 0.f;

    // stage layout: Ah 0(8K) Al 8192(8K) Bh 16384(16K) Bl 32768(16K) = 48K
    auto prefetch = [&](int k0, int st) {
        uint32_t base = sb + st * 49152;
        for (int u = tid; u < 512; u += 256) {
            int r = u >> 3, c = u & 7;
            uint32_t sw = swz((uint32_t)(r * 128 + c * 16));
            size_t ao = (size_t)(m0 + r) * K + k0 + c * 8;
            cp16(base + sw, Ah + ao);
            cp16(base + 8192 + sw, Al + ao);
        }
        for (int u = tid; u < 1024; u += 256) {
            int r = u >> 3, c = u & 7;
            uint32_t sw = swz((uint32_t)(r * 128 + c * 16));
            size_t bo = (size_t)r * K + k0 + c * 8;
            cp16(base + 16384 + sw, Bh + bo);
            cp16(base + 32768 + sw, Bl + bo);
        }
        CP_COMMIT();
    };

    const int nck = K / 64;
    prefetch(0, 0);
    for (int ck = 0; ck < nck; ck++) {
        if (ck + 1 < nck) { prefetch((ck + 1) * 64, (ck + 1) & 1); cp_wait<1>(); }
        else cp_wait<0>();
        __syncthreads();
        const uint32_t base = sb + (ck & 1) * 49152;
#pragma unroll
        for (int ks = 0; ks < 4; ks++) {
            const int kb = ks * 16;
            uint32_t a_h[2][4], a_l[2][4];
#pragma unroll
            for (int mt = 0; mt < 2; mt++) {
                int row = wm + mt * 16 + (lane & 15);
                int colb = (kb + ((lane >> 4) * 8)) * 2;
                uint32_t sw = swz((uint32_t)(row * 128 + colb));
                LDSM4(a_h[mt], base + sw);
                LDSM4(a_l[mt], base + 8192 + sw);
            }
            uint32_t b_h[2][4], b_l[2][4];
#pragma unroll
            for (int np = 0; np < 2; np++) {
                int row = wn + np * 16 + ((lane >> 4) * 8) + (lane & 7);
                int colb = (kb + (((lane >> 3) & 1) * 8)) * 2;
                uint32_t sw = swz((uint32_t)(row * 128 + colb));
                LDSM4(b_h[np], base + 16384 + sw);
                LDSM4(b_l[np], base + 32768 + sw);
            }
#pragma unroll
            for (int mt = 0; mt < 2; mt++)
#pragma unroll
                for (int np = 0; np < 2; np++) {
                    MMA16816(acc[mt][np*2],   a_h[mt], b_h[np][0], b_h[np][1]);
                    MMA16816(acc[mt][np*2],   a_l[mt], b_h[np][0], b_h[np][1]);
                    MMA16816(acc[mt][np*2],   a_h[mt], b_l[np][0], b_l[np][1]);
                    MMA16816(acc[mt][np*2+1], a_h[mt], b_h[np][2], b_h[np][3]);
                    MMA16816(acc[mt][np*2+1], a_l[mt], b_h[np][2], b_h[np][3]);
                    MMA16816(acc[mt][np*2+1], a_h[mt], b_l[np][2], b_l[np][3]);
                }
        }
        __syncthreads();
    }

#pragma unroll
    for (int mt = 0; mt < 2; mt++)
#pragma unroll
        for (int j = 0; j < 4; j++) {
            int row = m0 + wm + mt * 16 + (lane >> 2);
            int col = wn + j * 8 + (lane & 3) * 2;
            if (SPLIT) {
                float v0 = acc[mt][j][0] * oscale, v1 = acc[mt][j][1] * oscale;
                float v2 = acc[mt][j][2] * oscale, v3 = acc[mt][j][3] * oscale;
                uint32_t h0 = pk2(v0, v1), h1 = pk2(v2, v3);
                *(uint32_t*)(Ch + (size_t)row * 128 + col) = h0;
                *(uint32_t*)(Cl + (size_t)row * 128 + col) = pk2(v0 - lo_f(h0), v1 - hi_f(h0));
                *(uint32_t*)(Ch + (size_t)(row + 8) * 128 + col) = h1;
                *(uint32_t*)(Cl + (size_t)(row + 8) * 128 + col) = pk2(v2 - lo_f(h1), v3 - hi_f(h1));
            } else {
                *(float2*)(C + (size_t)row * 128 + col) =
                    make_float2(acc[mt][j][0], acc[mt][j][1]);
                *(float2*)(C + (size_t)(row + 8) * 128 + col) =
                    make_float2(acc[mt][j][2], acc[mt][j][3]);
            }
        }
}

// ---------------------------------------------------------------------------
// Flash attention, mma.sync bf16 split, persistent CTAs + atomic work queue.
// BM=64, BN=64, D=128. 128 threads, 2 CTAs/SM. Heavy q-blocks dispensed first.
// ---------------------------------------------------------------------------
__global__ __launch_bounds__(128, 2) void flash_mma(
    const bf16* __restrict__ qh, const bf16* __restrict__ ql,
    const bf16* __restrict__ kh, const bf16* __restrict__ kl,
    const bf16* __restrict__ vh, const bf16* __restrict__ vl,
    bf16* __restrict__ oh, bf16* __restrict__ ol) {
    extern __shared__ char smem[];
    const uint32_t sb = su32(smem);
    const uint32_t oQh = 0, oQl = 16384, oKh = 32768, oKl = 49152,
                   oVh = 65536, oVl = 81920;
    volatile unsigned* slot = (volatile unsigned*)(smem + 98304);
    const int tid = threadIdx.x, lane = tid & 31, warp = tid >> 5;
    const int wm = warp * 16;
    const int gr = lane >> 2, j2 = (lane & 3) * 2;

    while (true) {
        if (tid == 0) *slot = atomicAdd(&g_ctr, 1u);
        __syncthreads();
        unsigned r = *slot;
        __syncthreads();
        if (r >= 256u) break;
        const int mt = 63 - (int)(r >> 2), b = (int)(r & 3);
        const int m0 = mt * 64, ntiles = mt + 1;
        const size_t boff = (size_t)b * TLEN * DDIM;
        const bf16 *Qh = qh + boff, *Ql = ql + boff, *Kh = kh + boff,
                   *Kl = kl + boff, *Vh = vh + boff, *Vl = vl + boff;

        auto loadKV = [&](int n0) {
            for (int u = tid; u < 1024; u += 128) {
                int rr = u >> 4, cc = u & 15;
                uint32_t sw = sw256(rr, cc * 16);
                size_t src = (size_t)(n0 + rr) * 128 + cc * 8;
                cp16(sb + oKh + sw, Kh + src);
                cp16(sb + oKl + sw, Kl + src);
                cp16(sb + oVh + sw, Vh + src);
                cp16(sb + oVl + sw, Vl + src);
            }
            CP_COMMIT();
        };

        for (int u = tid; u < 1024; u += 128) {
            int rr = u >> 4, cc = u & 15;
            uint32_t sw = sw256(rr, cc * 16);
            size_t src = (size_t)(m0 + rr) * 128 + cc * 8;
            cp16(sb + oQh + sw, Qh + src);
            cp16(sb + oQl + sw, Ql + src);
        }
        loadKV(0);
        cp_wait<0>();
        __syncthreads();

        float o[16][4];
#pragma unroll
        for (int i = 0; i < 16; i++)
#pragma unroll
            for (int u = 0; u < 4; u++) o[i][u] = 0.f;
        float rm[2] = {-INFINITY, -INFINITY}, rl[2] = {0.f, 0.f};

        for (int nt = 0; nt < ntiles; nt++) {
            // ---- S = Q K^T (3-pass split) ----
            float s[8][4];
#pragma unroll
            for (int i = 0; i < 8; i++)
#pragma unroll
                for (int u = 0; u < 4; u++) s[i][u] = 0.f;
#pragma unroll
            for (int ks = 0; ks < 8; ks++) {
                uint32_t qa_h[4], qa_l[4];
                {
                    int row = wm + (lane & 15);
                    int cb = ks * 32 + ((lane >> 4) << 4);
                    uint32_t sw = sw256(row, cb);
                    LDSM4(qa_h, sb + oQh + sw);
                    LDSM4(qa_l, sb + oQl + sw);
                }
#pragma unroll
                for (int pr = 0; pr < 4; pr++) {
                    uint32_t kb_h[4], kb_l[4];
                    int row = pr * 16 + ((lane >> 4) << 3) + (lane & 7);
                    int cb = ks * 32 + (((lane >> 3) & 1) << 4);
                    uint32_t sw = sw256(row, cb);
                    LDSM4(kb_h, sb + oKh + sw);
                    LDSM4(kb_l, sb + oKl + sw);
                    MMA16816(s[pr*2],   qa_h, kb_h[0], kb_h[1]);
                    MMA16816(s[pr*2],   qa_l, kb_h[0], kb_h[1]);
                    MMA16816(s[pr*2],   qa_h, kb_l[0], kb_l[1]);
                    MMA16816(s[pr*2+1], qa_h, kb_h[2], kb_h[3]);
                    MMA16816(s[pr*2+1], qa_l, kb_h[2], kb_h[3]);
                    MMA16816(s[pr*2+1], qa_h, kb_l[2], kb_l[3]);
                }
            }

            // ---- causal mask on diagonal tile ----
            if (nt == ntiles - 1) {
#pragma unroll
                for (int nt8 = 0; nt8 < 8; nt8++) {
#pragma unroll
                    for (int c = 0; c < 4; c++) {
                        int col = nt8 * 8 + j2 + (c & 1);
                        int row = wm + gr + ((c >> 1) << 3);
                        if (col > row) s[nt8][c] = -1e30f;
                    }
                }
            }

            // ---- online softmax ----
            float mx0 = -INFINITY, mx1 = -INFINITY;
#pragma unroll
            for (int i = 0; i < 8; i++) {
                mx0 = fmaxf(mx0, fmaxf(s[i][0], s[i][1]));
                mx1 = fmaxf(mx1, fmaxf(s[i][2], s[i][3]));
            }
            mx0 = fmaxf(mx0, __shfl_xor_sync(0xffffffffu, mx0, 1));
            mx0 = fmaxf(mx0, __shfl_xor_sync(0xffffffffu, mx0, 2));
            mx1 = fmaxf(mx1, __shfl_xor_sync(0xffffffffu, mx1, 1));
            mx1 = fmaxf(mx1, __shfl_xor_sync(0xffffffffu, mx1, 2));
            float mn0 = fmaxf(rm[0], mx0), mn1 = fmaxf(rm[1], mx1);
            float sc0 = ex2(rm[0] - mn0), sc1 = ex2(rm[1] - mn1);
            float sum0 = 0.f, sum1 = 0.f;
#pragma unroll
            for (int i = 0; i < 8; i++) {
                s[i][0] = ex2(s[i][0] - mn0); sum0 += s[i][0];
                s[i][1] = ex2(s[i][1] - mn0); sum0 += s[i][1];
                s[i][2] = ex2(s[i][2] - mn1); sum1 += s[i][2];
                s[i][3] = ex2(s[i][3] - mn1); sum1 += s[i][3];
            }
            sum0 += __shfl_xor_sync(0xffffffffu, sum0, 1);
            sum0 += __shfl_xor_sync(0xffffffffu, sum0, 2);
            sum1 += __shfl_xor_sync(0xffffffffu, sum1, 1);
            sum1 += __shfl_xor_sync(0xffffffffu, sum1, 2);
            rl[0] = rl[0] * sc0 + sum0; rl[1] = rl[1] * sc1 + sum1;
            rm[0] = mn0; rm[1] = mn1;
#pragma unroll
            for (int i = 0; i < 16; i++) {
                o[i][0] *= sc0; o[i][1] *= sc0; o[i][2] *= sc1; o[i][3] *= sc1;
            }

            // ---- pack P to bf16 hi/lo (A-fragment layout) ----
            uint32_t ph[8][2], pl[8][2];
#pragma unroll
            for (int i = 0; i < 8; i++) {
                uint32_t h0 = pk2(s[i][0], s[i][1]);
                uint32_t h1 = pk2(s[i][2], s[i][3]);
                ph[i][0] = h0; ph[i][1] = h1;
                pl[i][0] = pk2(s[i][0] - lo_f(h0), s[i][1] - hi_f(h0));
                pl[i][1] = pk2(s[i][2] - lo_f(h1), s[i][3] - hi_f(h1));
            }

            // ---- O += P V (3-pass split) ----
#pragma unroll
            for (int kk = 0; kk < 4; kk++) {
                uint32_t pa_h[4] = {ph[kk*2][0], ph[kk*2][1], ph[kk*2+1][0], ph[kk*2+1][1]};
                uint32_t pa_l[4] = {pl[kk*2][0], pl[kk*2][1], pl[kk*2+1][0], pl[kk*2+1][1]};
#pragma unroll
                for (int dt = 0; dt < 8; dt++) {
                    uint32_t vf_h[4], vf_l[4];
                    int row = kk * 16 + (lane & 7) + (((lane >> 3) & 1) << 3);
                    int cb = dt * 32 + ((lane >> 4) << 4);
                    uint32_t sw = sw256(row, cb);
                    LDSM4T(vf_h, sb + oVh + sw);
                    LDSM4T(vf_l, sb + oVl + sw);
                    MMA16816(o[dt*2],   pa_h, vf_h[0], vf_h[1]);
                    MMA16816(o[dt*2],   pa_l, vf_h[0], vf_h[1]);
                    MMA16816(o[dt*2],   pa_h, vf_l[0], vf_l[1]);
                    MMA16816(o[dt*2+1], pa_h, vf_h[2], vf_h[3]);
                    MMA16816(o[dt*2+1], pa_l, vf_h[2], vf_h[3]);
                    MMA16816(o[dt*2+1], pa_h, vf_l[2], vf_l[3]);
                }
            }

            __syncthreads();
            if (nt + 1 < ntiles) {
                loadKV((nt + 1) * 64);
                cp_wait<0>();
            }
            __syncthreads();
        }

        // ---- epilogue ----
        float inv0 = 1.f / rl[0], inv1 = 1.f / rl[1];
        size_t row0 = (size_t)b * TLEN + m0 + wm + gr;
#pragma unroll
        for (int dt = 0; dt < 16; dt++) {
            int col = dt * 8 + j2;
            float v0 = o[dt][0] * inv0, v1 = o[dt][1] * inv0;
            float v2 = o[dt][2] * inv1, v3 = o[dt][3] * inv1;
            uint32_t h0 = pk2(v0, v1), h1 = pk2(v2, v3);
            *(uint32_t*)(oh + row0 * 128 + col) = h0;
            *(uint32_t*)(ol + row0 * 128 + col) = pk2(v0 - lo_f(h0), v1 - hi_f(h0));
            *(uint32_t*)(oh + (row0 + 8) * 128 + col) = h1;
            *(uint32_t*)(ol + (row0 + 8) * 128 + col) = pk2(v2 - lo_f(h1), v3 - hi_f(h1));
        }
    }
}

// ---------------------------------------------------------------------------
extern "C" void kernel_launch(void* const* d_in, const int* in_sizes, int n_in,
                              void* d_out, int out_size) {
    const float* x  = (const float*)d_in[0];
    const float* Wk = (const float*)d_in[1];
    const float* Wq = (const float*)d_in[2];
    const float* Wv = (const float*)d_in[3];
    const float* Wp = (const float*)d_in[4];
    float* out = (float*)d_out;

    bf16 *xh, *xl, *wth, *wtl, *wpth, *wptl;
    bf16 *qh, *ql, *kh, *kl, *vh, *vl, *oh, *ol;
    void* ctr;
    cudaGetSymbolAddress((void**)&xh, g_xh);   cudaGetSymbolAddress((void**)&xl, g_xl);
    cudaGetSymbolAddress((void**)&wth, g_wth); cudaGetSymbolAddress((void**)&wtl, g_wtl);
    cudaGetSymbolAddress((void**)&wpth, g_wpth); cudaGetSymbolAddress((void**)&wptl, g_wptl);
    cudaGetSymbolAddress((void**)&qh, g_qh);   cudaGetSymbolAddress((void**)&ql, g_ql);
    cudaGetSymbolAddress((void**)&kh, g_kh);   cudaGetSymbolAddress((void**)&kl, g_kl);
    cudaGetSymbolAddress((void**)&vh, g_vh);   cudaGetSymbolAddress((void**)&vl, g_vl);
    cudaGetSymbolAddress((void**)&oh, g_oh);   cudaGetSymbolAddress((void**)&ol, g_ol);
    cudaGetSymbolAddress(&ctr, g_ctr);

    const int mm_smem = 98304;    // 2 stages x 48KB
    const int fa_smem = 98304 + 128;
    cudaFuncSetAttribute(mm_bf16<1>, cudaFuncAttributeMaxDynamicSharedMemorySize, mm_smem);
    cudaFuncSetAttribute(mm_bf16<0>, cudaFuncAttributeMaxDynamicSharedMemorySize, mm_smem);
    cudaFuncSetAttribute(flash_mma, cudaFuncAttributeMaxDynamicSharedMemorySize, fa_smem);

    split_f32<<<MTOT * EDIM / 4 / 256, 256>>>(x, xh, xl, MTOT * EDIM / 4);
    convert_w<<<(3 * DDIM * EDIM + 255) / 256, 256>>>(Wq, Wk, Wv, Wp, wth, wtl, wpth, wptl);

    mm_bf16<1><<<MTOT / 64, 256, mm_smem>>>(xh, xl, wth, wtl,
                                            nullptr, qh, ql, QSCALE, EDIM);
    mm_bf16<1><<<MTOT / 64, 256, mm_smem>>>(xh, xl, wth + 1 * DDIM * EDIM, wtl + 1 * DDIM * EDIM,
                                            nullptr, kh, kl, 1.f, EDIM);
    mm_bf16<1><<<MTOT / 64, 256, mm_smem>>>(xh, xl, wth + 2 * DDIM * EDIM, wtl + 2 * DDIM * EDIM,
                                            nullptr, vh, vl, 1.f, EDIM);

    cudaMemsetAsync(ctr, 0, sizeof(unsigned int));
    flash_mma<<<296, 128, fa_smem>>>(qh, ql, kh, kl, vh, vl, oh, ol);

    mm_bf16<0><<<MTOT / 64, 256, mm_smem>>>(oh, ol, wpth, wptl,
                                            out, nullptr, nullptr, 1.f, DDIM);
}

// round 7
// speedup vs baseline: 1.3919x; 1.3919x over previous
#include <cuda_runtime.h>
#include <cuda_bf16.h>
#include <math.h>
#include <stdint.h>

#define BATCH 4
#define TLEN  4096
#define EDIM  1024
#define DDIM  128
#define MTOT  (BATCH*TLEN)
typedef __nv_bfloat16 bf16;

// q pre-scale: 1/sqrt(128) * log2(e)
#define QSCALE ((float)(0.08838834764831843 * 1.4426950408889634))

// ---------------- device scratch ----------------
__device__ bf16 g_xh[(size_t)MTOT*EDIM];
__device__ bf16 g_xl[(size_t)MTOT*EDIM];
__device__ bf16 g_wth[3*DDIM*EDIM];
__device__ bf16 g_wtl[3*DDIM*EDIM];
__device__ bf16 g_wpth[DDIM*DDIM];
__device__ bf16 g_wptl[DDIM*DDIM];
__device__ bf16 g_qh[(size_t)MTOT*DDIM], g_ql[(size_t)MTOT*DDIM];
__device__ bf16 g_kh[(size_t)MTOT*DDIM], g_kl[(size_t)MTOT*DDIM];
__device__ bf16 g_vh[(size_t)MTOT*DDIM], g_vl[(size_t)MTOT*DDIM];
__device__ bf16 g_oh[(size_t)MTOT*DDIM], g_ol[(size_t)MTOT*DDIM];

// ---------------- helpers ----------------
__device__ __forceinline__ uint32_t su32(const void* p) {
    return (uint32_t)__cvta_generic_to_shared(p);
}
__device__ __forceinline__ void cp16(uint32_t dst, const void* src) {
    asm volatile("cp.async.cg.shared.global [%0], [%1], 16;" :: "r"(dst), "l"(src));
}
#define CP_COMMIT() asm volatile("cp.async.commit_group;" ::: "memory")
template<int N> __device__ __forceinline__ void cp_wait() {
    asm volatile("cp.async.wait_group %0;" :: "n"(N) : "memory");
}
__device__ __forceinline__ uint32_t swz(uint32_t off) {       // 128B rows
    return off ^ ((off >> 3) & 0x70);
}
__device__ __forceinline__ uint32_t sw256(int r, int cb) {    // 256B rows
    return (uint32_t)(r * 256 + (cb ^ ((r & 7) << 4)));
}
#define LDSM4(r, addr) \
    asm volatile("ldmatrix.sync.aligned.m8n8.x4.shared.b16 {%0,%1,%2,%3}, [%4];" \
        : "=r"((r)[0]), "=r"((r)[1]), "=r"((r)[2]), "=r"((r)[3]) : "r"(addr))
#define LDSM4T(r, addr) \
    asm volatile("ldmatrix.sync.aligned.m8n8.x4.trans.shared.b16 {%0,%1,%2,%3}, [%4];" \
        : "=r"((r)[0]), "=r"((r)[1]), "=r"((r)[2]), "=r"((r)[3]) : "r"(addr))
#define MMA16816(d, a, b0, b1) \
    asm volatile("mma.sync.aligned.m16n8k16.row.col.f32.bf16.bf16.f32 " \
        "{%0,%1,%2,%3}, {%4,%5,%6,%7}, {%8,%9}, {%0,%1,%2,%3};" \
        : "+f"((d)[0]), "+f"((d)[1]), "+f"((d)[2]), "+f"((d)[3]) \
        : "r"((a)[0]), "r"((a)[1]), "r"((a)[2]), "r"((a)[3]), "r"(b0), "r"(b1))

__device__ __forceinline__ uint32_t pk2(float lo, float hi) { // {low:lo, high:hi}
    uint32_t r;
    asm("cvt.rn.bf16x2.f32 %0, %1, %2;" : "=r"(r) : "f"(hi), "f"(lo));
    return r;
}
__device__ __forceinline__ float lo_f(uint32_t h) { return __uint_as_float(h << 16); }
__device__ __forceinline__ float hi_f(uint32_t h) { return __uint_as_float(h & 0xffff0000u); }
__device__ __forceinline__ float ex2(float x) {
    float y; asm("ex2.approx.f32 %0, %1;" : "=f"(y) : "f"(x)); return y;
}

// ---------------- split fp32 -> bf16 hi/lo ----------------
__global__ __launch_bounds__(256) void split_f32(const float* __restrict__ s,
                                                 bf16* __restrict__ h,
                                                 bf16* __restrict__ l, int n4) {
    int idx = blockIdx.x * 256 + threadIdx.x;
    if (idx >= n4) return;
    float4 v = ((const float4*)s)[idx];
    float vv[4] = {v.x, v.y, v.z, v.w};
    uint32_t h0 = pk2(vv[0], vv[1]), h1 = pk2(vv[2], vv[3]);
    uint32_t l0 = pk2(vv[0] - lo_f(h0), vv[1] - hi_f(h0));
    uint32_t l1 = pk2(vv[2] - lo_f(h1), vv[3] - hi_f(h1));
    ((uint32_t*)h)[idx*2] = h0; ((uint32_t*)h)[idx*2+1] = h1;
    ((uint32_t*)l)[idx*2] = l0; ((uint32_t*)l)[idx*2+1] = l1;
}

// ---------------- transpose + split weights ----------------
__global__ __launch_bounds__(256) void convert_w(
    const float* __restrict__ wq, const float* __restrict__ wk,
    const float* __restrict__ wv, const float* __restrict__ wp,
    bf16* __restrict__ wth, bf16* __restrict__ wtl,
    bf16* __restrict__ wpth, bf16* __restrict__ wptl) {
    int idx = blockIdx.x * 256 + threadIdx.x;
    if (idx < 3 * DDIM * EDIM) {
        int k = idx & (EDIM - 1), n = (idx >> 10) & (DDIM - 1), w = idx >> 17;
        const float* W = (w == 0) ? wq : ((w == 1) ? wk : wv);
        float v = W[(size_t)k * DDIM + n];
        bf16 h = __float2bfloat16(v);
        wth[idx] = h; wtl[idx] = __float2bfloat16(v - __bfloat162float(h));
    }
    if (idx < DDIM * DDIM) {
        int k = idx & 127, n = idx >> 7;
        float v = wp[(size_t)k * DDIM + n];
        bf16 h = __float2bfloat16(v);
        wpth[idx] = h; wptl[idx] = __float2bfloat16(v - __bfloat162float(h));
    }
}

// ---------------------------------------------------------------------------
// C[M,128] = A[M,K] @ Bt[128,K]^T, split bf16, 3-pass, double-buffered.
// BM=64, BN=128, 256 threads (8 warps: 2m x 4n), 48KB/stage x2 = 96KB.
// ---------------------------------------------------------------------------
template<int SPLIT>
__global__ __launch_bounds__(256, 2) void mm_bf16(
    const bf16* __restrict__ Ah, const bf16* __restrict__ Al,
    const bf16* __restrict__ Bh, const bf16* __restrict__ Bl,
    float* __restrict__ C, bf16* __restrict__ Ch, bf16* __restrict__ Cl,
    float oscale, int K) {
    extern __shared__ char smem[];
    const uint32_t sb = su32(smem);
    const int tid = threadIdx.x, lane = tid & 31, warp = tid >> 5;
    const int wm = (warp & 1) * 32, wn = (warp >> 1) * 32;
    const int m0 = blockIdx.x * 64;

    float acc[2][4][4];
#pragma unroll
    for (int i = 0; i < 2; i++)
#pragma unroll
        for (int j = 0; j < 4; j++)
#pragma unroll
            for (int u = 0; u < 4; u++) acc[i][j][u] = 0.f;

    auto prefetch = [&](int k0, int st) {
        uint32_t base = sb + st * 49152;
        for (int u = tid; u < 512; u += 256) {
            int r = u >> 3, c = u & 7;
            uint32_t sw = swz((uint32_t)(r * 128 + c * 16));
            size_t ao = (size_t)(m0 + r) * K + k0 + c * 8;
            cp16(base + sw, Ah + ao);
            cp16(base + 8192 + sw, Al + ao);
        }
        for (int u = tid; u < 1024; u += 256) {
            int r = u >> 3, c = u & 7;
            uint32_t sw = swz((uint32_t)(r * 128 + c * 16));
            size_t bo = (size_t)r * K + k0 + c * 8;
            cp16(base + 16384 + sw, Bh + bo);
            cp16(base + 32768 + sw, Bl + bo);
        }
        CP_COMMIT();
    };

    const int nck = K / 64;
    prefetch(0, 0);
    for (int ck = 0; ck < nck; ck++) {
        if (ck + 1 < nck) { prefetch((ck + 1) * 64, (ck + 1) & 1); cp_wait<1>(); }
        else cp_wait<0>();
        __syncthreads();
        const uint32_t base = sb + (ck & 1) * 49152;
#pragma unroll
        for (int ks = 0; ks < 4; ks++) {
            const int kb = ks * 16;
            uint32_t a_h[2][4], a_l[2][4];
#pragma unroll
            for (int mt = 0; mt < 2; mt++) {
                int row = wm + mt * 16 + (lane & 15);
                int colb = (kb + ((lane >> 4) * 8)) * 2;
                uint32_t sw = swz((uint32_t)(row * 128 + colb));
                LDSM4(a_h[mt], base + sw);
                LDSM4(a_l[mt], base + 8192 + sw);
            }
            uint32_t b_h[2][4], b_l[2][4];
#pragma unroll
            for (int np = 0; np < 2; np++) {
                int row = wn + np * 16 + ((lane >> 4) * 8) + (lane & 7);
                int colb = (kb + (((lane >> 3) & 1) * 8)) * 2;
                uint32_t sw = swz((uint32_t)(row * 128 + colb));
                LDSM4(b_h[np], base + 16384 + sw);
                LDSM4(b_l[np], base + 32768 + sw);
            }
#pragma unroll
            for (int mt = 0; mt < 2; mt++)
#pragma unroll
                for (int np = 0; np < 2; np++) {
                    MMA16816(acc[mt][np*2],   a_h[mt], b_h[np][0], b_h[np][1]);
                    MMA16816(acc[mt][np*2],   a_l[mt], b_h[np][0], b_h[np][1]);
                    MMA16816(acc[mt][np*2],   a_h[mt], b_l[np][0], b_l[np][1]);
                    MMA16816(acc[mt][np*2+1], a_h[mt], b_h[np][2], b_h[np][3]);
                    MMA16816(acc[mt][np*2+1], a_l[mt], b_h[np][2], b_h[np][3]);
                    MMA16816(acc[mt][np*2+1], a_h[mt], b_l[np][2], b_l[np][3]);
                }
        }
        __syncthreads();
    }

#pragma unroll
    for (int mt = 0; mt < 2; mt++)
#pragma unroll
        for (int j = 0; j < 4; j++) {
            int row = m0 + wm + mt * 16 + (lane >> 2);
            int col = wn + j * 8 + (lane & 3) * 2;
            if (SPLIT) {
                float v0 = acc[mt][j][0] * oscale, v1 = acc[mt][j][1] * oscale;
                float v2 = acc[mt][j][2] * oscale, v3 = acc[mt][j][3] * oscale;
                uint32_t h0 = pk2(v0, v1), h1 = pk2(v2, v3);
                *(uint32_t*)(Ch + (size_t)row * 128 + col) = h0;
                *(uint32_t*)(Cl + (size_t)row * 128 + col) = pk2(v0 - lo_f(h0), v1 - hi_f(h0));
                *(uint32_t*)(Ch + (size_t)(row + 8) * 128 + col) = h1;
                *(uint32_t*)(Cl + (size_t)(row + 8) * 128 + col) = pk2(v2 - lo_f(h1), v3 - hi_f(h1));
            } else {
                *(float2*)(C + (size_t)row * 128 + col) =
                    make_float2(acc[mt][j][0], acc[mt][j][1]);
                *(float2*)(C + (size_t)(row + 8) * 128 + col) =
                    make_float2(acc[mt][j][2], acc[mt][j][3]);
            }
        }
}

// ---------------------------------------------------------------------------
// Flash attention, mma.sync bf16. Q in registers; K double-buffered (hi only),
// V single-buffered; pipelined cp.async. Static grid=256, pair-balanced map.
// smem: K0 16K | K1 16K | Vh 16K | Vl 16K = 64KB. 2 CTAs/SM.
// ---------------------------------------------------------------------------
__global__ __launch_bounds__(128, 2) void flash_mma(
    const bf16* __restrict__ qh, const bf16* __restrict__ ql,
    const bf16* __restrict__ kh,
    const bf16* __restrict__ vh, const bf16* __restrict__ vl,
    bf16* __restrict__ oh, bf16* __restrict__ ol) {
    extern __shared__ char smem[];
    const uint32_t sb = su32(smem);
    const uint32_t oK0 = 0, oK1 = 16384, oVh = 32768, oVl = 49152;
    const int tid = threadIdx.x, lane = tid & 31, warp = tid >> 5;
    const int wm = warp * 16;
    const int gr = lane >> 2, j2 = (lane & 3) * 2;

    // pair-balanced mapping: bid & bid+148 co-reside; weights sum ~const
    const int bid = blockIdx.x;
    const int j = (bid < 148) ? bid : (403 - bid);
    const int mt = 63 - (j >> 2), b = j & 3;
    const int m0 = mt * 64, ntiles = mt + 1;
    const size_t boff = (size_t)b * TLEN * DDIM;
    const bf16 *Qh = qh + boff, *Ql = ql + boff, *Kh = kh + boff,
               *Vh = vh + boff, *Vl = vl + boff;

    auto loadK = [&](int n0, uint32_t dst) {     // kh only, 16KB
        for (int u = tid; u < 1024; u += 128) {
            int rr = u >> 4, cc = u & 15;
            cp16(dst + sw256(rr, cc * 16), Kh + (size_t)(n0 + rr) * 128 + cc * 8);
        }
        CP_COMMIT();
    };
    auto loadV = [&](int n0) {                   // vh+vl, 32KB
        for (int u = tid; u < 1024; u += 128) {
            int rr = u >> 4, cc = u & 15;
            uint32_t sw = sw256(rr, cc * 16);
            size_t src = (size_t)(n0 + rr) * 128 + cc * 8;
            cp16(sb + oVh + sw, Vh + src);
            cp16(sb + oVl + sw, Vl + src);
        }
        CP_COMMIT();
    };

    // stage Q into V buffers, prefetch K0
    for (int u = tid; u < 1024; u += 128) {
        int rr = u >> 4, cc = u & 15;
        uint32_t sw = sw256(rr, cc * 16);
        size_t src = (size_t)(m0 + rr) * 128 + cc * 8;
        cp16(sb + oVh + sw, Qh + src);
        cp16(sb + oVl + sw, Ql + src);
    }
    CP_COMMIT();
    loadK(0, sb + oK0);
    cp_wait<1>();          // Q staged (K0 may be in flight)
    __syncthreads();

    // Q fragments to registers: 8 k-steps x 4 regs, hi and lo
    uint32_t qa_h[8][4], qa_l[8][4];
#pragma unroll
    for (int ks = 0; ks < 8; ks++) {
        int row = wm + (lane & 15);
        int cb = ks * 32 + ((lane >> 4) << 4);
        uint32_t sw = sw256(row, cb);
        LDSM4(qa_h[ks], sb + oVh + sw);
        LDSM4(qa_l[ks], sb + oVl + sw);
    }

    float o[16][4];
#pragma unroll
    for (int i = 0; i < 16; i++)
#pragma unroll
        for (int u = 0; u < 4; u++) o[i][u] = 0.f;
    float rm[2] = {-INFINITY, -INFINITY}, rl[2] = {0.f, 0.f};

    for (int nt = 0; nt < ntiles; nt++) {
        cp_wait<0>();           // K_nt ready (and V buffer free for reuse)
        __syncthreads();        // all warps done with Q-frags/prev PV

        loadV(nt * 64);
        const bool hasNext = (nt + 1 < ntiles);
        if (hasNext) loadK((nt + 1) * 64, sb + ((nt + 1) & 1 ? oK1 : oK0));

        const uint32_t kbuf = sb + ((nt & 1) ? oK1 : oK0);

        // ---- S = Qh*Kh + Ql*Kh (2-pass) ----
        float s[8][4];
#pragma unroll
        for (int i = 0; i < 8; i++)
#pragma unroll
            for (int u = 0; u < 4; u++) s[i][u] = 0.f;
#pragma unroll
        for (int ks = 0; ks < 8; ks++) {
#pragma unroll
            for (int pr = 0; pr < 4; pr++) {
                uint32_t kb_h[4];
                int row = pr * 16 + ((lane >> 4) << 3) + (lane & 7);
                int cb = ks * 32 + (((lane >> 3) & 1) << 4);
                LDSM4(kb_h, kbuf + sw256(row, cb));
                MMA16816(s[pr*2],   qa_h[ks], kb_h[0], kb_h[1]);
                MMA16816(s[pr*2],   qa_l[ks], kb_h[0], kb_h[1]);
                MMA16816(s[pr*2+1], qa_h[ks], kb_h[2], kb_h[3]);
                MMA16816(s[pr*2+1], qa_l[ks], kb_h[2], kb_h[3]);
            }
        }

        // ---- causal mask on diagonal tile ----
        if (nt == ntiles - 1) {
#pragma unroll
            for (int nt8 = 0; nt8 < 8; nt8++) {
#pragma unroll
                for (int c = 0; c < 4; c++) {
                    int col = nt8 * 8 + j2 + (c & 1);
                    int row = wm + gr + ((c >> 1) << 3);
                    if (col > row) s[nt8][c] = -1e30f;
                }
            }
        }

        // ---- online softmax ----
        float mx0 = -INFINITY, mx1 = -INFINITY;
#pragma unroll
        for (int i = 0; i < 8; i++) {
            mx0 = fmaxf(mx0, fmaxf(s[i][0], s[i][1]));
            mx1 = fmaxf(mx1, fmaxf(s[i][2], s[i][3]));
        }
        mx0 = fmaxf(mx0, __shfl_xor_sync(0xffffffffu, mx0, 1));
        mx0 = fmaxf(mx0, __shfl_xor_sync(0xffffffffu, mx0, 2));
        mx1 = fmaxf(mx1, __shfl_xor_sync(0xffffffffu, mx1, 1));
        mx1 = fmaxf(mx1, __shfl_xor_sync(0xffffffffu, mx1, 2));
        float mn0 = fmaxf(rm[0], mx0), mn1 = fmaxf(rm[1], mx1);
        float sc0 = ex2(rm[0] - mn0), sc1 = ex2(rm[1] - mn1);
        float sum0 = 0.f, sum1 = 0.f;
#pragma unroll
        for (int i = 0; i < 8; i++) {
            s[i][0] = ex2(s[i][0] - mn0); sum0 += s[i][0];
            s[i][1] = ex2(s[i][1] - mn0); sum0 += s[i][1];
            s[i][2] = ex2(s[i][2] - mn1); sum1 += s[i][2];
            s[i][3] = ex2(s[i][3] - mn1); sum1 += s[i][3];
        }
        sum0 += __shfl_xor_sync(0xffffffffu, sum0, 1);
        sum0 += __shfl_xor_sync(0xffffffffu, sum0, 2);
        sum1 += __shfl_xor_sync(0xffffffffu, sum1, 1);
        sum1 += __shfl_xor_sync(0xffffffffu, sum1, 2);
        rl[0] = rl[0] * sc0 + sum0; rl[1] = rl[1] * sc1 + sum1;
        rm[0] = mn0; rm[1] = mn1;
#pragma unroll
        for (int i = 0; i < 16; i++) {
            o[i][0] *= sc0; o[i][1] *= sc0; o[i][2] *= sc1; o[i][3] *= sc1;
        }

        // ---- pack P to bf16 hi/lo (A-fragment layout) ----
        uint32_t ph[8][2], pl[8][2];
#pragma unroll
        for (int i = 0; i < 8; i++) {
            uint32_t h0 = pk2(s[i][0], s[i][1]);
            uint32_t h1 = pk2(s[i][2], s[i][3]);
            ph[i][0] = h0; ph[i][1] = h1;
            pl[i][0] = pk2(s[i][0] - lo_f(h0), s[i][1] - hi_f(h0));
            pl[i][1] = pk2(s[i][2] - lo_f(h1), s[i][3] - hi_f(h1));
        }

        // wait for V (K_{nt+1} may still be in flight)
        if (hasNext) cp_wait<1>(); else cp_wait<0>();
        __syncthreads();

        // ---- O += P V (3-pass) ----
#pragma unroll
        for (int kk = 0; kk < 4; kk++) {
            uint32_t pa_h[4] = {ph[kk*2][0], ph[kk*2][1], ph[kk*2+1][0], ph[kk*2+1][1]};
            uint32_t pa_l[4] = {pl[kk*2][0], pl[kk*2][1], pl[kk*2+1][0], pl[kk*2+1][1]};
#pragma unroll
            for (int dt = 0; dt < 8; dt++) {
                uint32_t vf_h[4], vf_l[4];
                int row = kk * 16 + (lane & 7) + (((lane >> 3) & 1) << 3);
                int cb = dt * 32 + ((lane >> 4) << 4);
                uint32_t sw = sw256(row, cb);
                LDSM4T(vf_h, sb + oVh + sw);
                LDSM4T(vf_l, sb + oVl + sw);
                MMA16816(o[dt*2],   pa_h, vf_h[0], vf_h[1]);
                MMA16816(o[dt*2],   pa_l, vf_h[0], vf_h[1]);
                MMA16816(o[dt*2],   pa_h, vf_l[0], vf_l[1]);
                MMA16816(o[dt*2+1], pa_h, vf_h[2], vf_h[3]);
                MMA16816(o[dt*2+1], pa_l, vf_h[2], vf_h[3]);
                MMA16816(o[dt*2+1], pa_h, vf_l[2], vf_l[3]);
            }
        }
    }

    // ---- epilogue ----
    float inv0 = 1.f / rl[0], inv1 = 1.f / rl[1];
    size_t row0 = (size_t)b * TLEN + m0 + wm + gr;
#pragma unroll
    for (int dt = 0; dt < 16; dt++) {
        int col = dt * 8 + j2;
        float v0 = o[dt][0] * inv0, v1 = o[dt][1] * inv0;
        float v2 = o[dt][2] * inv1, v3 = o[dt][3] * inv1;
        uint32_t h0 = pk2(v0, v1), h1 = pk2(v2, v3);
        *(uint32_t*)(oh + row0 * 128 + col) = h0;
        *(uint32_t*)(ol + row0 * 128 + col) = pk2(v0 - lo_f(h0), v1 - hi_f(h0));
        *(uint32_t*)(oh + (row0 + 8) * 128 + col) = h1;
        *(uint32_t*)(ol + (row0 + 8) * 128 + col) = pk2(v2 - lo_f(h1), v3 - hi_f(h1));
    }
}

// ---------------------------------------------------------------------------
extern "C" void kernel_launch(void* const* d_in, const int* in_sizes, int n_in,
                              void* d_out, int out_size) {
    const float* x  = (const float*)d_in[0];
    const float* Wk = (const float*)d_in[1];
    const float* Wq = (const float*)d_in[2];
    const float* Wv = (const float*)d_in[3];
    const float* Wp = (const float*)d_in[4];
    float* out = (float*)d_out;

    bf16 *xh, *xl, *wth, *wtl, *wpth, *wptl;
    bf16 *qh, *ql, *kh, *kl, *vh, *vl, *oh, *ol;
    cudaGetSymbolAddress((void**)&xh, g_xh);   cudaGetSymbolAddress((void**)&xl, g_xl);
    cudaGetSymbolAddress((void**)&wth, g_wth); cudaGetSymbolAddress((void**)&wtl, g_wtl);
    cudaGetSymbolAddress((void**)&wpth, g_wpth); cudaGetSymbolAddress((void**)&wptl, g_wptl);
    cudaGetSymbolAddress((void**)&qh, g_qh);   cudaGetSymbolAddress((void**)&ql, g_ql);
    cudaGetSymbolAddress((void**)&kh, g_kh);   cudaGetSymbolAddress((void**)&kl, g_kl);
    cudaGetSymbolAddress((void**)&vh, g_vh);   cudaGetSymbolAddress((void**)&vl, g_vl);
    cudaGetSymbolAddress((void**)&oh, g_oh);   cudaGetSymbolAddress((void**)&ol, g_ol);

    const int mm_smem = 98304;   // 2 stages x 48KB
    const int fa_smem = 65536;   // K0 16K + K1 16K + Vh 16K + Vl 16K
    cudaFuncSetAttribute(mm_bf16<1>, cudaFuncAttributeMaxDynamicSharedMemorySize, mm_smem);
    cudaFuncSetAttribute(mm_bf16<0>, cudaFuncAttributeMaxDynamicSharedMemorySize, mm_smem);
    cudaFuncSetAttribute(flash_mma, cudaFuncAttributeMaxDynamicSharedMemorySize, fa_smem);

    split_f32<<<MTOT * EDIM / 4 / 256, 256>>>(x, xh, xl, MTOT * EDIM / 4);
    convert_w<<<(3 * DDIM * EDIM + 255) / 256, 256>>>(Wq, Wk, Wv, Wp, wth, wtl, wpth, wptl);

    mm_bf16<1><<<MTOT / 64, 256, mm_smem>>>(xh, xl, wth, wtl,
                                            nullptr, qh, ql, QSCALE, EDIM);
    mm_bf16<1><<<MTOT / 64, 256, mm_smem>>>(xh, xl, wth + 1 * DDIM * EDIM, wtl + 1 * DDIM * EDIM,
                                            nullptr, kh, kl, 1.f, EDIM);
    mm_bf16<1><<<MTOT / 64, 256, mm_smem>>>(xh, xl, wth + 2 * DDIM * EDIM, wtl + 2 * DDIM * EDIM,
                                            nullptr, vh, vl, 1.f, EDIM);

    flash_mma<<<256, 128, fa_smem>>>(qh, ql, kh, vh, vl, oh, ol);

    mm_bf16<0><<<MTOT / 64, 256, mm_smem>>>(oh, ol, wpth, wptl,
                                            out, nullptr, nullptr, 1.f, DDIM);
}

// round 8
// speedup vs baseline: 1.4713x; 1.0571x over previous
#include <cuda_runtime.h>
#include <cuda_fp16.h>
#include <math.h>
#include <stdint.h>

#define BATCH 4
#define TLEN  4096
#define EDIM  1024
#define DDIM  128
#define MTOT  (BATCH*TLEN)
typedef __half hlf;

// q pre-scale: 1/sqrt(128) * log2(e)
#define QSCALE ((float)(0.08838834764831843 * 1.4426950408889634))

// ---------------- device scratch ----------------
__device__ hlf g_xh[(size_t)MTOT*EDIM];
__device__ hlf g_xl[(size_t)MTOT*EDIM];
__device__ hlf g_wth[3*DDIM*EDIM];
__device__ hlf g_wtl[3*DDIM*EDIM];
__device__ hlf g_wpth[DDIM*DDIM];
__device__ hlf g_wptl[DDIM*DDIM];
__device__ hlf g_qkvh[(size_t)3*MTOT*DDIM];   // planes: q, k, v (hi)
__device__ hlf g_qkvl[(size_t)3*MTOT*DDIM];   // planes: q, k, v (lo)
__device__ hlf g_oh[(size_t)MTOT*DDIM], g_ol[(size_t)MTOT*DDIM];

// ---------------- helpers ----------------
__device__ __forceinline__ uint32_t su32(const void* p) {
    return (uint32_t)__cvta_generic_to_shared(p);
}
__device__ __forceinline__ void cp16(uint32_t dst, const void* src) {
    asm volatile("cp.async.cg.shared.global [%0], [%1], 16;" :: "r"(dst), "l"(src));
}
#define CP_COMMIT() asm volatile("cp.async.commit_group;" ::: "memory")
template<int N> __device__ __forceinline__ void cp_wait() {
    asm volatile("cp.async.wait_group %0;" :: "n"(N) : "memory");
}
__device__ __forceinline__ uint32_t swz(uint32_t off) {       // 128B rows
    return off ^ ((off >> 3) & 0x70);
}
__device__ __forceinline__ uint32_t sw256(int r, int cb) {    // 256B rows
    return (uint32_t)(r * 256 + (cb ^ ((r & 7) << 4)));
}
#define LDSM4(r, addr) \
    asm volatile("ldmatrix.sync.aligned.m8n8.x4.shared.b16 {%0,%1,%2,%3}, [%4];" \
        : "=r"((r)[0]), "=r"((r)[1]), "=r"((r)[2]), "=r"((r)[3]) : "r"(addr))
#define LDSM4T(r, addr) \
    asm volatile("ldmatrix.sync.aligned.m8n8.x4.trans.shared.b16 {%0,%1,%2,%3}, [%4];" \
        : "=r"((r)[0]), "=r"((r)[1]), "=r"((r)[2]), "=r"((r)[3]) : "r"(addr))
#define MMA16816(d, a, b0, b1) \
    asm volatile("mma.sync.aligned.m16n8k16.row.col.f32.f16.f16.f32 " \
        "{%0,%1,%2,%3}, {%4,%5,%6,%7}, {%8,%9}, {%0,%1,%2,%3};" \
        : "+f"((d)[0]), "+f"((d)[1]), "+f"((d)[2]), "+f"((d)[3]) \
        : "r"((a)[0]), "r"((a)[1]), "r"((a)[2]), "r"((a)[3]), "r"(b0), "r"(b1))

__device__ __forceinline__ uint32_t pk2(float lo, float hi) { // pack {low:lo, high:hi}
    uint32_t r;
    asm("cvt.rn.f16x2.f32 %0, %1, %2;" : "=r"(r) : "f"(hi), "f"(lo));
    return r;
}
__device__ __forceinline__ float lo_f(uint32_t h) {
    __half2 x = *(__half2*)&h; return __low2float(x);
}
__device__ __forceinline__ float hi_f(uint32_t h) {
    __half2 x = *(__half2*)&h; return __high2float(x);
}
__device__ __forceinline__ float ex2(float x) {
    float y; asm("ex2.approx.f32 %0, %1;" : "=f"(y) : "f"(x)); return y;
}

// ---------------- split fp32 -> fp16 hi/lo ----------------
__global__ __launch_bounds__(256) void split_f32(const float* __restrict__ s,
                                                 hlf* __restrict__ h,
                                                 hlf* __restrict__ l, int n4) {
    int idx = blockIdx.x * 256 + threadIdx.x;
    if (idx >= n4) return;
    float4 v = ((const float4*)s)[idx];
    float vv[4] = {v.x, v.y, v.z, v.w};
    uint32_t h0 = pk2(vv[0], vv[1]), h1 = pk2(vv[2], vv[3]);
    uint32_t l0 = pk2(vv[0] - lo_f(h0), vv[1] - hi_f(h0));
    uint32_t l1 = pk2(vv[2] - lo_f(h1), vv[3] - hi_f(h1));
    ((uint32_t*)h)[idx*2] = h0; ((uint32_t*)h)[idx*2+1] = h1;
    ((uint32_t*)l)[idx*2] = l0; ((uint32_t*)l)[idx*2+1] = l1;
}

// ---------------- transpose + split weights ----------------
__global__ __launch_bounds__(256) void convert_w(
    const float* __restrict__ wq, const float* __restrict__ wk,
    const float* __restrict__ wv, const float* __restrict__ wp,
    hlf* __restrict__ wth, hlf* __restrict__ wtl,
    hlf* __restrict__ wpth, hlf* __restrict__ wptl) {
    int idx = blockIdx.x * 256 + threadIdx.x;
    if (idx < 3 * DDIM * EDIM) {
        int k = idx & (EDIM - 1), n = (idx >> 10) & (DDIM - 1), w = idx >> 17;
        const float* W = (w == 0) ? wq : ((w == 1) ? wk : wv);
        float v = W[(size_t)k * DDIM + n];
        hlf h = __float2half_rn(v);
        wth[idx] = h; wtl[idx] = __float2half_rn(v - __half2float(h));
    }
    if (idx < DDIM * DDIM) {
        int k = idx & 127, n = idx >> 7;
        float v = wp[(size_t)k * DDIM + n];
        hlf h = __float2half_rn(v);
        wpth[idx] = h; wptl[idx] = __float2half_rn(v - __half2float(h));
    }
}

// ---------------------------------------------------------------------------
// GEMM core: C[M,128] = A[M,K] @ Bt[128,K]^T, fp16 split 3-pass, dbl-buffered.
// BM=64, BN=128, 256 threads (8 warps: 2m x 4n), 48KB/stage x2 = 96KB.
// QKV=1: blockIdx.y selects weight plane, writes fp16 hi/lo (+QSCALE on w=0).
// QKV=0: writes fp32 C.
// ---------------------------------------------------------------------------
template<int QKV>
__global__ __launch_bounds__(256, 2) void mm_hf(
    const hlf* __restrict__ Ah, const hlf* __restrict__ Al,
    const hlf* __restrict__ Bh0, const hlf* __restrict__ Bl0,
    float* __restrict__ C, hlf* __restrict__ Ch0, hlf* __restrict__ Cl0,
    int K) {
    extern __shared__ char smem[];
    const uint32_t sb = su32(smem);
    const int tid = threadIdx.x, lane = tid & 31, warp = tid >> 5;
    const int wm = (warp & 1) * 32, wn = (warp >> 1) * 32;
    const int m0 = blockIdx.x * 64;

    const int w = QKV ? blockIdx.y : 0;
    const hlf* Bh = Bh0 + (size_t)w * DDIM * EDIM;
    const hlf* Bl = Bl0 + (size_t)w * DDIM * EDIM;
    hlf* Ch = QKV ? (Ch0 + (size_t)w * MTOT * DDIM) : nullptr;
    hlf* Cl = QKV ? (Cl0 + (size_t)w * MTOT * DDIM) : nullptr;
    const float oscale = (QKV && w == 0) ? QSCALE : 1.f;

    float acc[2][4][4];
#pragma unroll
    for (int i = 0; i < 2; i++)
#pragma unroll
        for (int j = 0; j < 4; j++)
#pragma unroll
            for (int u = 0; u < 4; u++) acc[i][j][u] = 0.f;

    auto prefetch = [&](int k0, int st) {
        uint32_t base = sb + st * 49152;
        for (int u = tid; u < 512; u += 256) {
            int r = u >> 3, c = u & 7;
            uint32_t sw = swz((uint32_t)(r * 128 + c * 16));
            size_t ao = (size_t)(m0 + r) * K + k0 + c * 8;
            cp16(base + sw, Ah + ao);
            cp16(base + 8192 + sw, Al + ao);
        }
        for (int u = tid; u < 1024; u += 256) {
            int r = u >> 3, c = u & 7;
            uint32_t sw = swz((uint32_t)(r * 128 + c * 16));
            size_t bo = (size_t)r * K + k0 + c * 8;
            cp16(base + 16384 + sw, Bh + bo);
            cp16(base + 32768 + sw, Bl + bo);
        }
        CP_COMMIT();
    };

    const int nck = K / 64;
    prefetch(0, 0);
    for (int ck = 0; ck < nck; ck++) {
        if (ck + 1 < nck) { prefetch((ck + 1) * 64, (ck + 1) & 1); cp_wait<1>(); }
        else cp_wait<0>();
        __syncthreads();
        const uint32_t base = sb + (ck & 1) * 49152;
#pragma unroll
        for (int ks = 0; ks < 4; ks++) {
            const int kb = ks * 16;
            uint32_t a_h[2][4], a_l[2][4];
#pragma unroll
            for (int mt = 0; mt < 2; mt++) {
                int row = wm + mt * 16 + (lane & 15);
                int colb = (kb + ((lane >> 4) * 8)) * 2;
                uint32_t sw = swz((uint32_t)(row * 128 + colb));
                LDSM4(a_h[mt], base + sw);
                LDSM4(a_l[mt], base + 8192 + sw);
            }
            uint32_t b_h[2][4], b_l[2][4];
#pragma unroll
            for (int np = 0; np < 2; np++) {
                int row = wn + np * 16 + ((lane >> 4) * 8) + (lane & 7);
                int colb = (kb + (((lane >> 3) & 1) * 8)) * 2;
                uint32_t sw = swz((uint32_t)(row * 128 + colb));
                LDSM4(b_h[np], base + 16384 + sw);
                LDSM4(b_l[np], base + 32768 + sw);
            }
#pragma unroll
            for (int mt = 0; mt < 2; mt++)
#pragma unroll
                for (int np = 0; np < 2; np++) {
                    MMA16816(acc[mt][np*2],   a_h[mt], b_h[np][0], b_h[np][1]);
                    MMA16816(acc[mt][np*2],   a_l[mt], b_h[np][0], b_h[np][1]);
                    MMA16816(acc[mt][np*2],   a_h[mt], b_l[np][0], b_l[np][1]);
                    MMA16816(acc[mt][np*2+1], a_h[mt], b_h[np][2], b_h[np][3]);
                    MMA16816(acc[mt][np*2+1], a_l[mt], b_h[np][2], b_h[np][3]);
                    MMA16816(acc[mt][np*2+1], a_h[mt], b_l[np][2], b_l[np][3]);
                }
        }
        __syncthreads();
    }

#pragma unroll
    for (int mt = 0; mt < 2; mt++)
#pragma unroll
        for (int j = 0; j < 4; j++) {
            int row = m0 + wm + mt * 16 + (lane >> 2);
            int col = wn + j * 8 + (lane & 3) * 2;
            if (QKV) {
                float v0 = acc[mt][j][0] * oscale, v1 = acc[mt][j][1] * oscale;
                float v2 = acc[mt][j][2] * oscale, v3 = acc[mt][j][3] * oscale;
                uint32_t h0 = pk2(v0, v1), h1 = pk2(v2, v3);
                *(uint32_t*)(Ch + (size_t)row * 128 + col) = h0;
                *(uint32_t*)(Cl + (size_t)row * 128 + col) = pk2(v0 - lo_f(h0), v1 - hi_f(h0));
                *(uint32_t*)(Ch + (size_t)(row + 8) * 128 + col) = h1;
                *(uint32_t*)(Cl + (size_t)(row + 8) * 128 + col) = pk2(v2 - lo_f(h1), v3 - hi_f(h1));
            } else {
                *(float2*)(C + (size_t)row * 128 + col) =
                    make_float2(acc[mt][j][0], acc[mt][j][1]);
                *(float2*)(C + (size_t)(row + 8) * 128 + col) =
                    make_float2(acc[mt][j][2], acc[mt][j][3]);
            }
        }
}

// ---------------------------------------------------------------------------
// Flash attention, mma.sync fp16. Q 1-pass in registers; K 1-pass dbl-buffered;
// V hi/lo single-buffered, PV 3-pass. Static grid=256, pair-balanced map.
// smem: K0 16K | K1 16K | Vh 16K | Vl 16K = 64KB. 2 CTAs/SM.
// ---------------------------------------------------------------------------
__global__ __launch_bounds__(128, 2) void flash_mma(
    const hlf* __restrict__ qh, const hlf* __restrict__ kh,
    const hlf* __restrict__ vh, const hlf* __restrict__ vl,
    hlf* __restrict__ oh, hlf* __restrict__ ol) {
    extern __shared__ char smem[];
    const uint32_t sb = su32(smem);
    const uint32_t oK0 = 0, oK1 = 16384, oVh = 32768, oVl = 49152;
    const int tid = threadIdx.x, lane = tid & 31, warp = tid >> 5;
    const int wm = warp * 16;
    const int gr = lane >> 2, j2 = (lane & 3) * 2;

    // pair-balanced mapping: bid & bid+148 co-reside; weights sum ~const
    const int bid = blockIdx.x;
    const int j = (bid < 148) ? bid : (403 - bid);
    const int mt = 63 - (j >> 2), b = j & 3;
    const int m0 = mt * 64, ntiles = mt + 1;
    const size_t boff = (size_t)b * TLEN * DDIM;
    const hlf *Qh = qh + boff, *Kh = kh + boff, *Vh = vh + boff, *Vl = vl + boff;

    auto loadK = [&](int n0, uint32_t dst) {     // kh only, 16KB
        for (int u = tid; u < 1024; u += 128) {
            int rr = u >> 4, cc = u & 15;
            cp16(dst + sw256(rr, cc * 16), Kh + (size_t)(n0 + rr) * 128 + cc * 8);
        }
        CP_COMMIT();
    };
    auto loadV = [&](int n0) {                   // vh+vl, 32KB
        for (int u = tid; u < 1024; u += 128) {
            int rr = u >> 4, cc = u & 15;
            uint32_t sw = sw256(rr, cc * 16);
            size_t src = (size_t)(n0 + rr) * 128 + cc * 8;
            cp16(sb + oVh + sw, Vh + src);
            cp16(sb + oVl + sw, Vl + src);
        }
        CP_COMMIT();
    };

    // stage Q (hi only) into Vh buffer, prefetch K0
    for (int u = tid; u < 1024; u += 128) {
        int rr = u >> 4, cc = u & 15;
        cp16(sb + oVh + sw256(rr, cc * 16), Qh + (size_t)(m0 + rr) * 128 + cc * 8);
    }
    CP_COMMIT();
    loadK(0, sb + oK0);
    cp_wait<1>();          // Q staged (K0 may be in flight)
    __syncthreads();

    // Q fragments to registers: 8 k-steps x 4 regs
    uint32_t qa[8][4];
#pragma unroll
    for (int ks = 0; ks < 8; ks++) {
        int row = wm + (lane & 15);
        int cb = ks * 32 + ((lane >> 4) << 4);
        LDSM4(qa[ks], sb + oVh + sw256(row, cb));
    }

    float o[16][4];
#pragma unroll
    for (int i = 0; i < 16; i++)
#pragma unroll
        for (int u = 0; u < 4; u++) o[i][u] = 0.f;
    float rm[2] = {-INFINITY, -INFINITY}, rl[2] = {0.f, 0.f};

    for (int nt = 0; nt < ntiles; nt++) {
        cp_wait<0>();           // K_nt ready, V buffer free
        __syncthreads();

        loadV(nt * 64);
        const bool hasNext = (nt + 1 < ntiles);
        if (hasNext) loadK((nt + 1) * 64, sb + ((nt + 1) & 1 ? oK1 : oK0));

        const uint32_t kbuf = sb + ((nt & 1) ? oK1 : oK0);

        // ---- S = Q K^T (1-pass fp16) ----
        float s[8][4];
#pragma unroll
        for (int i = 0; i < 8; i++)
#pragma unroll
            for (int u = 0; u < 4; u++) s[i][u] = 0.f;
#pragma unroll
        for (int ks = 0; ks < 8; ks++) {
#pragma unroll
            for (int pr = 0; pr < 4; pr++) {
                uint32_t kb_h[4];
                int row = pr * 16 + ((lane >> 4) << 3) + (lane & 7);
                int cb = ks * 32 + (((lane >> 3) & 1) << 4);
                LDSM4(kb_h, kbuf + sw256(row, cb));
                MMA16816(s[pr*2],   qa[ks], kb_h[0], kb_h[1]);
                MMA16816(s[pr*2+1], qa[ks], kb_h[2], kb_h[3]);
            }
        }

        // ---- causal mask on diagonal tile ----
        if (nt == ntiles - 1) {
#pragma unroll
            for (int nt8 = 0; nt8 < 8; nt8++) {
#pragma unroll
                for (int c = 0; c < 4; c++) {
                    int col = nt8 * 8 + j2 + (c & 1);
                    int row = wm + gr + ((c >> 1) << 3);
                    if (col > row) s[nt8][c] = -1e30f;
                }
            }
        }

        // ---- online softmax ----
        float mx0 = -INFINITY, mx1 = -INFINITY;
#pragma unroll
        for (int i = 0; i < 8; i++) {
            mx0 = fmaxf(mx0, fmaxf(s[i][0], s[i][1]));
            mx1 = fmaxf(mx1, fmaxf(s[i][2], s[i][3]));
        }
        mx0 = fmaxf(mx0, __shfl_xor_sync(0xffffffffu, mx0, 1));
        mx0 = fmaxf(mx0, __shfl_xor_sync(0xffffffffu, mx0, 2));
        mx1 = fmaxf(mx1, __shfl_xor_sync(0xffffffffu, mx1, 1));
        mx1 = fmaxf(mx1, __shfl_xor_sync(0xffffffffu, mx1, 2));
        float mn0 = fmaxf(rm[0], mx0), mn1 = fmaxf(rm[1], mx1);
        float sc0 = ex2(rm[0] - mn0), sc1 = ex2(rm[1] - mn1);
        float sum0 = 0.f, sum1 = 0.f;
#pragma unroll
        for (int i = 0; i < 8; i++) {
            s[i][0] = ex2(s[i][0] - mn0); sum0 += s[i][0];
            s[i][1] = ex2(s[i][1] - mn0); sum0 += s[i][1];
            s[i][2] = ex2(s[i][2] - mn1); sum1 += s[i][2];
            s[i][3] = ex2(s[i][3] - mn1); sum1 += s[i][3];
        }
        sum0 += __shfl_xor_sync(0xffffffffu, sum0, 1);
        sum0 += __shfl_xor_sync(0xffffffffu, sum0, 2);
        sum1 += __shfl_xor_sync(0xffffffffu, sum1, 1);
        sum1 += __shfl_xor_sync(0xffffffffu, sum1, 2);
        rl[0] = rl[0] * sc0 + sum0; rl[1] = rl[1] * sc1 + sum1;
        rm[0] = mn0; rm[1] = mn1;
#pragma unroll
        for (int i = 0; i < 16; i++) {
            o[i][0] *= sc0; o[i][1] *= sc0; o[i][2] *= sc1; o[i][3] *= sc1;
        }

        // ---- pack P to fp16 hi/lo (A-fragment layout) ----
        uint32_t ph[8][2], pl[8][2];
#pragma unroll
        for (int i = 0; i < 8; i++) {
            uint32_t h0 = pk2(s[i][0], s[i][1]);
            uint32_t h1 = pk2(s[i][2], s[i][3]);
            ph[i][0] = h0; ph[i][1] = h1;
            pl[i][0] = pk2(s[i][0] - lo_f(h0), s[i][1] - hi_f(h0));
            pl[i][1] = pk2(s[i][2] - lo_f(h1), s[i][3] - hi_f(h1));
        }

        // wait for V (K_{nt+1} may still be in flight)
        if (hasNext) cp_wait<1>(); else cp_wait<0>();
        __syncthreads();

        // ---- O += P V (3-pass) ----
#pragma unroll
        for (int kk = 0; kk < 4; kk++) {
            uint32_t pa_h[4] = {ph[kk*2][0], ph[kk*2][1], ph[kk*2+1][0], ph[kk*2+1][1]};
            uint32_t pa_l[4] = {pl[kk*2][0], pl[kk*2][1], pl[kk*2+1][0], pl[kk*2+1][1]};
#pragma unroll
            for (int dt = 0; dt < 8; dt++) {
                uint32_t vf_h[4], vf_l[4];
                int row = kk * 16 + (lane & 7) + (((lane >> 3) & 1) << 3);
                int cb = dt * 32 + ((lane >> 4) << 4);
                uint32_t sw = sw256(row, cb);
                LDSM4T(vf_h, sb + oVh + sw);
                LDSM4T(vf_l, sb + oVl + sw);
                MMA16816(o[dt*2],   pa_h, vf_h[0], vf_h[1]);
                MMA16816(o[dt*2],   pa_l, vf_h[0], vf_h[1]);
                MMA16816(o[dt*2],   pa_h, vf_l[0], vf_l[1]);
                MMA16816(o[dt*2+1], pa_h, vf_h[2], vf_h[3]);
                MMA16816(o[dt*2+1], pa_l, vf_h[2], vf_h[3]);
                MMA16816(o[dt*2+1], pa_h, vf_l[2], vf_l[3]);
            }
        }
    }

    // ---- epilogue ----
    float inv0 = 1.f / rl[0], inv1 = 1.f / rl[1];
    size_t row0 = (size_t)b * TLEN + m0 + wm + gr;
#pragma unroll
    for (int dt = 0; dt < 16; dt++) {
        int col = dt * 8 + j2;
        float v0 = o[dt][0] * inv0, v1 = o[dt][1] * inv0;
        float v2 = o[dt][2] * inv1, v3 = o[dt][3] * inv1;
        uint32_t h0 = pk2(v0, v1), h1 = pk2(v2, v3);
        *(uint32_t*)(oh + row0 * 128 + col) = h0;
        *(uint32_t*)(ol + row0 * 128 + col) = pk2(v0 - lo_f(h0), v1 - hi_f(h0));
        *(uint32_t*)(oh + (row0 + 8) * 128 + col) = h1;
        *(uint32_t*)(ol + (row0 + 8) * 128 + col) = pk2(v2 - lo_f(h1), v3 - hi_f(h1));
    }
}

// ---------------------------------------------------------------------------
extern "C" void kernel_launch(void* const* d_in, const int* in_sizes, int n_in,
                              void* d_out, int out_size) {
    const float* x  = (const float*)d_in[0];
    const float* Wk = (const float*)d_in[1];
    const float* Wq = (const float*)d_in[2];
    const float* Wv = (const float*)d_in[3];
    const float* Wp = (const float*)d_in[4];
    float* out = (float*)d_out;

    hlf *xh, *xl, *wth, *wtl, *wpth, *wptl, *qkvh, *qkvl, *oh, *ol;
    cudaGetSymbolAddress((void**)&xh, g_xh);     cudaGetSymbolAddress((void**)&xl, g_xl);
    cudaGetSymbolAddress((void**)&wth, g_wth);   cudaGetSymbolAddress((void**)&wtl, g_wtl);
    cudaGetSymbolAddress((void**)&wpth, g_wpth); cudaGetSymbolAddress((void**)&wptl, g_wptl);
    cudaGetSymbolAddress((void**)&qkvh, g_qkvh); cudaGetSymbolAddress((void**)&qkvl, g_qkvl);
    cudaGetSymbolAddress((void**)&oh, g_oh);     cudaGetSymbolAddress((void**)&ol, g_ol);

    const int mm_smem = 98304;   // 2 stages x 48KB
    const int fa_smem = 65536;   // K0 16K + K1 16K + Vh 16K + Vl 16K
    cudaFuncSetAttribute(mm_hf<1>, cudaFuncAttributeMaxDynamicSharedMemorySize, mm_smem);
    cudaFuncSetAttribute(mm_hf<0>, cudaFuncAttributeMaxDynamicSharedMemorySize, mm_smem);
    cudaFuncSetAttribute(flash_mma, cudaFuncAttributeMaxDynamicSharedMemorySize, fa_smem);

    split_f32<<<MTOT * EDIM / 4 / 256, 256>>>(x, xh, xl, MTOT * EDIM / 4);
    convert_w<<<(3 * DDIM * EDIM + 255) / 256, 256>>>(Wq, Wk, Wv, Wp, wth, wtl, wpth, wptl);

    // fused QKV: blockIdx.y = weight plane (0:q with QSCALE, 1:k, 2:v)
    mm_hf<1><<<dim3(MTOT / 64, 3), 256, mm_smem>>>(xh, xl, wth, wtl,
                                                   nullptr, qkvh, qkvl, EDIM);

    const size_t P = (size_t)MTOT * DDIM;
    flash_mma<<<256, 128, fa_smem>>>(qkvh, qkvh + P, qkvh + 2 * P, qkvl + 2 * P,
                                     oh, ol);

    mm_hf<0><<<MTOT / 64, 256, mm_smem>>>(oh, ol, wpth, wptl,
                                          out, nullptr, nullptr, DDIM);
}

// round 9
// speedup vs baseline: 1.8624x; 1.2658x over previous
#include <cuda_runtime.h>
#include <cuda_fp16.h>
#include <math.h>
#include <stdint.h>

#define BATCH 4
#define TLEN  4096
#define EDIM  1024
#define DDIM  128
#define MTOT  (BATCH*TLEN)
typedef __half hlf;

// q pre-scale: 1/sqrt(128) * log2(e)
#define QSCALE ((float)(0.08838834764831843 * 1.4426950408889634))

// ---------------- device scratch ----------------
__device__ hlf g_xh[(size_t)MTOT*EDIM];
__device__ hlf g_xl[(size_t)MTOT*EDIM];
__device__ hlf g_wth[3*DDIM*EDIM];
__device__ hlf g_wtl[3*DDIM*EDIM];
__device__ hlf g_wpth[DDIM*DDIM];
__device__ hlf g_wptl[DDIM*DDIM];
__device__ hlf g_qkvh[(size_t)3*MTOT*DDIM];   // planes: q, k, v (hi only)
__device__ hlf g_oh[(size_t)MTOT*DDIM], g_ol[(size_t)MTOT*DDIM];

// ---------------- helpers ----------------
__device__ __forceinline__ uint32_t su32(const void* p) {
    return (uint32_t)__cvta_generic_to_shared(p);
}
__device__ __forceinline__ void cp16(uint32_t dst, const void* src) {
    asm volatile("cp.async.cg.shared.global [%0], [%1], 16;" :: "r"(dst), "l"(src));
}
#define CP_COMMIT() asm volatile("cp.async.commit_group;" ::: "memory")
template<int N> __device__ __forceinline__ void cp_wait() {
    asm volatile("cp.async.wait_group %0;" :: "n"(N) : "memory");
}
__device__ __forceinline__ uint32_t swz(uint32_t off) {       // 128B rows
    return off ^ ((off >> 3) & 0x70);
}
__device__ __forceinline__ uint32_t sw256(int r, int cb) {    // 256B rows
    return (uint32_t)(r * 256 + (cb ^ ((r & 7) << 4)));
}
#define LDSM4(r, addr) \
    asm volatile("ldmatrix.sync.aligned.m8n8.x4.shared.b16 {%0,%1,%2,%3}, [%4];" \
        : "=r"((r)[0]), "=r"((r)[1]), "=r"((r)[2]), "=r"((r)[3]) : "r"(addr))
#define LDSM4T(r, addr) \
    asm volatile("ldmatrix.sync.aligned.m8n8.x4.trans.shared.b16 {%0,%1,%2,%3}, [%4];" \
        : "=r"((r)[0]), "=r"((r)[1]), "=r"((r)[2]), "=r"((r)[3]) : "r"(addr))
#define MMA16816(d, a, b0, b1) \
    asm volatile("mma.sync.aligned.m16n8k16.row.col.f32.f16.f16.f32 " \
        "{%0,%1,%2,%3}, {%4,%5,%6,%7}, {%8,%9}, {%0,%1,%2,%3};" \
        : "+f"((d)[0]), "+f"((d)[1]), "+f"((d)[2]), "+f"((d)[3]) \
        : "r"((a)[0]), "r"((a)[1]), "r"((a)[2]), "r"((a)[3]), "r"(b0), "r"(b1))

__device__ __forceinline__ uint32_t pk2(float lo, float hi) { // pack {low:lo, high:hi}
    uint32_t r;
    asm("cvt.rn.f16x2.f32 %0, %1, %2;" : "=r"(r) : "f"(hi), "f"(lo));
    return r;
}
__device__ __forceinline__ float lo_f(uint32_t h) {
    __half2 x = *(__half2*)&h; return __low2float(x);
}
__device__ __forceinline__ float hi_f(uint32_t h) {
    __half2 x = *(__half2*)&h; return __high2float(x);
}
__device__ __forceinline__ float ex2(float x) {
    float y; asm("ex2.approx.f32 %0, %1;" : "=f"(y) : "f"(x)); return y;
}

// ---------------- split fp32 -> fp16 hi/lo ----------------
__global__ __launch_bounds__(256) void split_f32(const float* __restrict__ s,
                                                 hlf* __restrict__ h,
                                                 hlf* __restrict__ l, int n4) {
    int idx = blockIdx.x * 256 + threadIdx.x;
    if (idx >= n4) return;
    float4 v = ((const float4*)s)[idx];
    float vv[4] = {v.x, v.y, v.z, v.w};
    uint32_t h0 = pk2(vv[0], vv[1]), h1 = pk2(vv[2], vv[3]);
    uint32_t l0 = pk2(vv[0] - lo_f(h0), vv[1] - hi_f(h0));
    uint32_t l1 = pk2(vv[2] - lo_f(h1), vv[3] - hi_f(h1));
    ((uint32_t*)h)[idx*2] = h0; ((uint32_t*)h)[idx*2+1] = h1;
    ((uint32_t*)l)[idx*2] = l0; ((uint32_t*)l)[idx*2+1] = l1;
}

// ---------------- transpose + split weights ----------------
__global__ __launch_bounds__(256) void convert_w(
    const float* __restrict__ wq, const float* __restrict__ wk,
    const float* __restrict__ wv, const float* __restrict__ wp,
    hlf* __restrict__ wth, hlf* __restrict__ wtl,
    hlf* __restrict__ wpth, hlf* __restrict__ wptl) {
    int idx = blockIdx.x * 256 + threadIdx.x;
    if (idx < 3 * DDIM * EDIM) {
        int k = idx & (EDIM - 1), n = (idx >> 10) & (DDIM - 1), w = idx >> 17;
        const float* W = (w == 0) ? wq : ((w == 1) ? wk : wv);
        float v = W[(size_t)k * DDIM + n];
        hlf h = __float2half_rn(v);
        wth[idx] = h; wtl[idx] = __float2half_rn(v - __half2float(h));
    }
    if (idx < DDIM * DDIM) {
        int k = idx & 127, n = idx >> 7;
        float v = wp[(size_t)k * DDIM + n];
        hlf h = __float2half_rn(v);
        wpth[idx] = h; wptl[idx] = __float2half_rn(v - __half2float(h));
    }
}

// ---------------------------------------------------------------------------
// GEMM core: C[M,128] = A[M,K] @ Bt[128,K]^T, fp16 split 3-pass, dbl-buffered.
// BM=64, BN=128, 256 threads (8 warps: 2m x 4n), 48KB/stage x2 = 96KB.
// QKV=1: blockIdx.y selects weight plane, writes fp16 hi only (+QSCALE on w=0).
// QKV=0: writes fp32 C.
// ---------------------------------------------------------------------------
template<int QKV>
__global__ __launch_bounds__(256, 2) void mm_hf(
    const hlf* __restrict__ Ah, const hlf* __restrict__ Al,
    const hlf* __restrict__ Bh0, const hlf* __restrict__ Bl0,
    float* __restrict__ C, hlf* __restrict__ Ch0, int K) {
    extern __shared__ char smem[];
    const uint32_t sb = su32(smem);
    const int tid = threadIdx.x, lane = tid & 31, warp = tid >> 5;
    const int wm = (warp & 1) * 32, wn = (warp >> 1) * 32;
    const int m0 = blockIdx.x * 64;

    const int w = QKV ? blockIdx.y : 0;
    const hlf* Bh = Bh0 + (size_t)w * DDIM * EDIM;
    const hlf* Bl = Bl0 + (size_t)w * DDIM * EDIM;
    hlf* Ch = QKV ? (Ch0 + (size_t)w * MTOT * DDIM) : nullptr;
    const float oscale = (QKV && w == 0) ? QSCALE : 1.f;

    float acc[2][4][4];
#pragma unroll
    for (int i = 0; i < 2; i++)
#pragma unroll
        for (int j = 0; j < 4; j++)
#pragma unroll
            for (int u = 0; u < 4; u++) acc[i][j][u] = 0.f;

    auto prefetch = [&](int k0, int st) {
        uint32_t base = sb + st * 49152;
        for (int u = tid; u < 512; u += 256) {
            int r = u >> 3, c = u & 7;
            uint32_t sw = swz((uint32_t)(r * 128 + c * 16));
            size_t ao = (size_t)(m0 + r) * K + k0 + c * 8;
            cp16(base + sw, Ah + ao);
            cp16(base + 8192 + sw, Al + ao);
        }
        for (int u = tid; u < 1024; u += 256) {
            int r = u >> 3, c = u & 7;
            uint32_t sw = swz((uint32_t)(r * 128 + c * 16));
            size_t bo = (size_t)r * K + k0 + c * 8;
            cp16(base + 16384 + sw, Bh + bo);
            cp16(base + 32768 + sw, Bl + bo);
        }
        CP_COMMIT();
    };

    const int nck = K / 64;
    prefetch(0, 0);
    for (int ck = 0; ck < nck; ck++) {
        if (ck + 1 < nck) { prefetch((ck + 1) * 64, (ck + 1) & 1); cp_wait<1>(); }
        else cp_wait<0>();
        __syncthreads();
        const uint32_t base = sb + (ck & 1) * 49152;
#pragma unroll
        for (int ks = 0; ks < 4; ks++) {
            const int kb = ks * 16;
            uint32_t a_h[2][4], a_l[2][4];
#pragma unroll
            for (int mt = 0; mt < 2; mt++) {
                int row = wm + mt * 16 + (lane & 15);
                int colb = (kb + ((lane >> 4) * 8)) * 2;
                uint32_t sw = swz((uint32_t)(row * 128 + colb));
                LDSM4(a_h[mt], base + sw);
                LDSM4(a_l[mt], base + 8192 + sw);
            }
            uint32_t b_h[2][4], b_l[2][4];
#pragma unroll
            for (int np = 0; np < 2; np++) {
                int row = wn + np * 16 + ((lane >> 4) * 8) + (lane & 7);
                int colb = (kb + (((lane >> 3) & 1) * 8)) * 2;
                uint32_t sw = swz((uint32_t)(row * 128 + colb));
                LDSM4(b_h[np], base + 16384 + sw);
                LDSM4(b_l[np], base + 32768 + sw);
            }
#pragma unroll
            for (int mt = 0; mt < 2; mt++)
#pragma unroll
                for (int np = 0; np < 2; np++) {
                    MMA16816(acc[mt][np*2],   a_h[mt], b_h[np][0], b_h[np][1]);
                    MMA16816(acc[mt][np*2],   a_l[mt], b_h[np][0], b_h[np][1]);
                    MMA16816(acc[mt][np*2],   a_h[mt], b_l[np][0], b_l[np][1]);
                    MMA16816(acc[mt][np*2+1], a_h[mt], b_h[np][2], b_h[np][3]);
                    MMA16816(acc[mt][np*2+1], a_l[mt], b_h[np][2], b_h[np][3]);
                    MMA16816(acc[mt][np*2+1], a_h[mt], b_l[np][2], b_l[np][3]);
                }
        }
        __syncthreads();
    }

#pragma unroll
    for (int mt = 0; mt < 2; mt++)
#pragma unroll
        for (int j = 0; j < 4; j++) {
            int row = m0 + wm + mt * 16 + (lane >> 2);
            int col = wn + j * 8 + (lane & 3) * 2;
            if (QKV) {
                float v0 = acc[mt][j][0] * oscale, v1 = acc[mt][j][1] * oscale;
                float v2 = acc[mt][j][2] * oscale, v3 = acc[mt][j][3] * oscale;
                *(uint32_t*)(Ch + (size_t)row * 128 + col) = pk2(v0, v1);
                *(uint32_t*)(Ch + (size_t)(row + 8) * 128 + col) = pk2(v2, v3);
            } else {
                *(float2*)(C + (size_t)row * 128 + col) =
                    make_float2(acc[mt][j][0], acc[mt][j][1]);
                *(float2*)(C + (size_t)(row + 8) * 128 + col) =
                    make_float2(acc[mt][j][2], acc[mt][j][3]);
            }
        }
}

// ---------------------------------------------------------------------------
// Flash attention, mma.sync fp16, single-pass QK and PV. Q in registers;
// K and V both double-buffered, joint prefetch 1 tile ahead.
// smem: K0 16K | K1 16K | V0 16K | V1 16K = 64KB. 2 CTAs/SM.
// ---------------------------------------------------------------------------
__global__ __launch_bounds__(128, 2) void flash_mma(
    const hlf* __restrict__ qh, const hlf* __restrict__ kh,
    const hlf* __restrict__ vh,
    hlf* __restrict__ oh, hlf* __restrict__ ol) {
    extern __shared__ char smem[];
    const uint32_t sb = su32(smem);
    const uint32_t oK0 = 0, oK1 = 16384, oV0 = 32768, oV1 = 49152;
    const int tid = threadIdx.x, lane = tid & 31, warp = tid >> 5;
    const int wm = warp * 16;
    const int gr = lane >> 2, j2 = (lane & 3) * 2;

    // pair-balanced mapping: bid & bid+148 co-reside; weights sum ~const
    const int bid = blockIdx.x;
    const int j = (bid < 148) ? bid : (403 - bid);
    const int mt = 63 - (j >> 2), b = j & 3;
    const int m0 = mt * 64, ntiles = mt + 1;
    const size_t boff = (size_t)b * TLEN * DDIM;
    const hlf *Qh = qh + boff, *Kh = kh + boff, *Vh = vh + boff;

    auto loadKV = [&](int n0, int st) {   // 16KB K + 16KB V, one group
        uint32_t kd = sb + (st ? oK1 : oK0), vd = sb + (st ? oV1 : oV0);
        for (int u = tid; u < 1024; u += 128) {
            int rr = u >> 4, cc = u & 15;
            uint32_t sw = sw256(rr, cc * 16);
            size_t src = (size_t)(n0 + rr) * 128 + cc * 8;
            cp16(kd + sw, Kh + src);
            cp16(vd + sw, Vh + src);
        }
        CP_COMMIT();
    };

    // stage Q into V1 buffer, then prefetch K0/V0
    for (int u = tid; u < 1024; u += 128) {
        int rr = u >> 4, cc = u & 15;
        cp16(sb + oV1 + sw256(rr, cc * 16), Qh + (size_t)(m0 + rr) * 128 + cc * 8);
    }
    CP_COMMIT();
    loadKV(0, 0);
    cp_wait<1>();          // Q staged (K0/V0 may be in flight)
    __syncthreads();

    // Q fragments to registers: 8 k-steps x 4 regs
    uint32_t qa[8][4];
#pragma unroll
    for (int ks = 0; ks < 8; ks++) {
        int row = wm + (lane & 15);
        int cb = ks * 32 + ((lane >> 4) << 4);
        LDSM4(qa[ks], sb + oV1 + sw256(row, cb));
    }

    float o[16][4];
#pragma unroll
    for (int i = 0; i < 16; i++)
#pragma unroll
        for (int u = 0; u < 4; u++) o[i][u] = 0.f;
    float rm[2] = {-INFINITY, -INFINITY}, rl[2] = {0.f, 0.f};

    for (int nt = 0; nt < ntiles; nt++) {
        cp_wait<0>();           // K_nt/V_nt ready
        __syncthreads();        // all warps done reading prev buffers / Q-stage

        if (nt + 1 < ntiles) loadKV((nt + 1) * 64, (nt + 1) & 1);

        const uint32_t kbuf = sb + ((nt & 1) ? oK1 : oK0);
        const uint32_t vbuf = sb + ((nt & 1) ? oV1 : oV0);

        // ---- S = Q K^T (1-pass fp16) ----
        float s[8][4];
#pragma unroll
        for (int i = 0; i < 8; i++)
#pragma unroll
            for (int u = 0; u < 4; u++) s[i][u] = 0.f;
#pragma unroll
        for (int ks = 0; ks < 8; ks++) {
#pragma unroll
            for (int pr = 0; pr < 4; pr++) {
                uint32_t kb_h[4];
                int row = pr * 16 + ((lane >> 4) << 3) + (lane & 7);
                int cb = ks * 32 + (((lane >> 3) & 1) << 4);
                LDSM4(kb_h, kbuf + sw256(row, cb));
                MMA16816(s[pr*2],   qa[ks], kb_h[0], kb_h[1]);
                MMA16816(s[pr*2+1], qa[ks], kb_h[2], kb_h[3]);
            }
        }

        // ---- causal mask on diagonal tile ----
        if (nt == ntiles - 1) {
#pragma unroll
            for (int nt8 = 0; nt8 < 8; nt8++) {
#pragma unroll
                for (int c = 0; c < 4; c++) {
                    int col = nt8 * 8 + j2 + (c & 1);
                    int row = wm + gr + ((c >> 1) << 3);
                    if (col > row) s[nt8][c] = -1e30f;
                }
            }
        }

        // ---- online softmax ----
        float mx0 = -INFINITY, mx1 = -INFINITY;
#pragma unroll
        for (int i = 0; i < 8; i++) {
            mx0 = fmaxf(mx0, fmaxf(s[i][0], s[i][1]));
            mx1 = fmaxf(mx1, fmaxf(s[i][2], s[i][3]));
        }
        mx0 = fmaxf(mx0, __shfl_xor_sync(0xffffffffu, mx0, 1));
        mx0 = fmaxf(mx0, __shfl_xor_sync(0xffffffffu, mx0, 2));
        mx1 = fmaxf(mx1, __shfl_xor_sync(0xffffffffu, mx1, 1));
        mx1 = fmaxf(mx1, __shfl_xor_sync(0xffffffffu, mx1, 2));
        float mn0 = fmaxf(rm[0], mx0), mn1 = fmaxf(rm[1], mx1);
        float sc0 = ex2(rm[0] - mn0), sc1 = ex2(rm[1] - mn1);
        float sum0 = 0.f, sum1 = 0.f;
#pragma unroll
        for (int i = 0; i < 8; i++) {
            s[i][0] = ex2(s[i][0] - mn0); sum0 += s[i][0];
            s[i][1] = ex2(s[i][1] - mn0); sum0 += s[i][1];
            s[i][2] = ex2(s[i][2] - mn1); sum1 += s[i][2];
            s[i][3] = ex2(s[i][3] - mn1); sum1 += s[i][3];
        }
        sum0 += __shfl_xor_sync(0xffffffffu, sum0, 1);
        sum0 += __shfl_xor_sync(0xffffffffu, sum0, 2);
        sum1 += __shfl_xor_sync(0xffffffffu, sum1, 1);
        sum1 += __shfl_xor_sync(0xffffffffu, sum1, 2);
        rl[0] = rl[0] * sc0 + sum0; rl[1] = rl[1] * sc1 + sum1;
        rm[0] = mn0; rm[1] = mn1;
#pragma unroll
        for (int i = 0; i < 16; i++) {
            o[i][0] *= sc0; o[i][1] *= sc0; o[i][2] *= sc1; o[i][3] *= sc1;
        }

        // ---- pack P to fp16 (A-fragment layout) ----
        uint32_t ph[8][2];
#pragma unroll
        for (int i = 0; i < 8; i++) {
            ph[i][0] = pk2(s[i][0], s[i][1]);
            ph[i][1] = pk2(s[i][2], s[i][3]);
        }

        // ---- O += P V (1-pass fp16) ----
#pragma unroll
        for (int kk = 0; kk < 4; kk++) {
            uint32_t pa[4] = {ph[kk*2][0], ph[kk*2][1], ph[kk*2+1][0], ph[kk*2+1][1]};
#pragma unroll
            for (int dt = 0; dt < 8; dt++) {
                uint32_t vf[4];
                int row = kk * 16 + (lane & 7) + (((lane >> 3) & 1) << 3);
                int cb = dt * 32 + ((lane >> 4) << 4);
                LDSM4T(vf, vbuf + sw256(row, cb));
                MMA16816(o[dt*2],   pa, vf[0], vf[1]);
                MMA16816(o[dt*2+1], pa, vf[2], vf[3]);
            }
        }
    }

    // ---- epilogue: normalize, split to fp16 hi/lo ----
    float inv0 = 1.f / rl[0], inv1 = 1.f / rl[1];
    size_t row0 = (size_t)b * TLEN + m0 + wm + gr;
#pragma unroll
    for (int dt = 0; dt < 16; dt++) {
        int col = dt * 8 + j2;
        float v0 = o[dt][0] * inv0, v1 = o[dt][1] * inv0;
        float v2 = o[dt][2] * inv1, v3 = o[dt][3] * inv1;
        uint32_t h0 = pk2(v0, v1), h1 = pk2(v2, v3);
        *(uint32_t*)(oh + row0 * 128 + col) = h0;
        *(uint32_t*)(ol + row0 * 128 + col) = pk2(v0 - lo_f(h0), v1 - hi_f(h0));
        *(uint32_t*)(oh + (row0 + 8) * 128 + col) = h1;
        *(uint32_t*)(ol + (row0 + 8) * 128 + col) = pk2(v2 - lo_f(h1), v3 - hi_f(h1));
    }
}

// ---------------------------------------------------------------------------
extern "C" void kernel_launch(void* const* d_in, const int* in_sizes, int n_in,
                              void* d_out, int out_size) {
    const float* x  = (const float*)d_in[0];
    const float* Wk = (const float*)d_in[1];
    const float* Wq = (const float*)d_in[2];
    const float* Wv = (const float*)d_in[3];
    const float* Wp = (const float*)d_in[4];
    float* out = (float*)d_out;

    hlf *xh, *xl, *wth, *wtl, *wpth, *wptl, *qkvh, *oh, *ol;
    cudaGetSymbolAddress((void**)&xh, g_xh);     cudaGetSymbolAddress((void**)&xl, g_xl);
    cudaGetSymbolAddress((void**)&wth, g_wth);   cudaGetSymbolAddress((void**)&wtl, g_wtl);
    cudaGetSymbolAddress((void**)&wpth, g_wpth); cudaGetSymbolAddress((void**)&wptl, g_wptl);
    cudaGetSymbolAddress((void**)&qkvh, g_qkvh);
    cudaGetSymbolAddress((void**)&oh, g_oh);     cudaGetSymbolAddress((void**)&ol, g_ol);

    const int mm_smem = 98304;   // 2 stages x 48KB
    const int fa_smem = 65536;   // K0 + K1 + V0 + V1
    cudaFuncSetAttribute(mm_hf<1>, cudaFuncAttributeMaxDynamicSharedMemorySize, mm_smem);
    cudaFuncSetAttribute(mm_hf<0>, cudaFuncAttributeMaxDynamicSharedMemorySize, mm_smem);
    cudaFuncSetAttribute(flash_mma, cudaFuncAttributeMaxDynamicSharedMemorySize, fa_smem);

    split_f32<<<MTOT * EDIM / 4 / 256, 256>>>(x, xh, xl, MTOT * EDIM / 4);
    convert_w<<<(3 * DDIM * EDIM + 255) / 256, 256>>>(Wq, Wk, Wv, Wp, wth, wtl, wpth, wptl);

    // fused QKV: blockIdx.y = weight plane (0:q with QSCALE, 1:k, 2:v)
    mm_hf<1><<<dim3(MTOT / 64, 3), 256, mm_smem>>>(xh, xl, wth, wtl,
                                                   nullptr, qkvh, EDIM);

    const size_t P = (size_t)MTOT * DDIM;
    flash_mma<<<256, 128, fa_smem>>>(qkvh, qkvh + P, qkvh + 2 * P, oh, ol);

    mm_hf<0><<<MTOT / 64, 256, mm_smem>>>(oh, ol, wpth, wptl, out, nullptr, DDIM);
}

// round 10
// speedup vs baseline: 2.5067x; 1.3459x over previous
#include <cuda_runtime.h>
#include <cuda_fp16.h>
#include <math.h>
#include <stdint.h>

#define BATCH 4
#define TLEN  4096
#define EDIM  1024
#define DDIM  128
#define MTOT  (BATCH*TLEN)
typedef __half hlf;

// q pre-scale: 1/sqrt(128) * log2(e)
#define QSCALE ((float)(0.08838834764831843 * 1.4426950408889634))

// ---------------- device scratch ----------------
__device__ hlf g_xh[(size_t)MTOT*EDIM];
__device__ hlf g_wth[3*DDIM*EDIM];            // Wq/Wk/Wv transposed, hi only
__device__ hlf g_wpth[DDIM*DDIM];             // Wp^T hi
__device__ hlf g_wptl[DDIM*DDIM];             // Wp^T lo
__device__ hlf g_qkvh[(size_t)3*MTOT*DDIM];   // planes: q, k, v
__device__ hlf g_oh[(size_t)MTOT*DDIM], g_ol[(size_t)MTOT*DDIM];

// ---------------- helpers ----------------
__device__ __forceinline__ uint32_t su32(const void* p) {
    return (uint32_t)__cvta_generic_to_shared(p);
}
__device__ __forceinline__ void cp16(uint32_t dst, const void* src) {
    asm volatile("cp.async.cg.shared.global [%0], [%1], 16;" :: "r"(dst), "l"(src));
}
#define CP_COMMIT() asm volatile("cp.async.commit_group;" ::: "memory")
template<int N> __device__ __forceinline__ void cp_wait() {
    asm volatile("cp.async.wait_group %0;" :: "n"(N) : "memory");
}
__device__ __forceinline__ uint32_t swz(uint32_t off) {       // 128B rows
    return off ^ ((off >> 3) & 0x70);
}
__device__ __forceinline__ uint32_t sw256(int r, int cb) {    // 256B rows
    return (uint32_t)(r * 256 + (cb ^ ((r & 7) << 4)));
}
#define LDSM4(r, addr) \
    asm volatile("ldmatrix.sync.aligned.m8n8.x4.shared.b16 {%0,%1,%2,%3}, [%4];" \
        : "=r"((r)[0]), "=r"((r)[1]), "=r"((r)[2]), "=r"((r)[3]) : "r"(addr))
#define LDSM4T(r, addr) \
    asm volatile("ldmatrix.sync.aligned.m8n8.x4.trans.shared.b16 {%0,%1,%2,%3}, [%4];" \
        : "=r"((r)[0]), "=r"((r)[1]), "=r"((r)[2]), "=r"((r)[3]) : "r"(addr))
#define MMA16816(d, a, b0, b1) \
    asm volatile("mma.sync.aligned.m16n8k16.row.col.f32.f16.f16.f32 " \
        "{%0,%1,%2,%3}, {%4,%5,%6,%7}, {%8,%9}, {%0,%1,%2,%3};" \
        : "+f"((d)[0]), "+f"((d)[1]), "+f"((d)[2]), "+f"((d)[3]) \
        : "r"((a)[0]), "r"((a)[1]), "r"((a)[2]), "r"((a)[3]), "r"(b0), "r"(b1))

__device__ __forceinline__ uint32_t pk2(float lo, float hi) { // pack {low:lo, high:hi}
    uint32_t r;
    asm("cvt.rn.f16x2.f32 %0, %1, %2;" : "=r"(r) : "f"(hi), "f"(lo));
    return r;
}
__device__ __forceinline__ float lo_f(uint32_t h) {
    __half2 x = *(__half2*)&h; return __low2float(x);
}
__device__ __forceinline__ float hi_f(uint32_t h) {
    __half2 x = *(__half2*)&h; return __high2float(x);
}
__device__ __forceinline__ float ex2(float x) {
    float y; asm("ex2.approx.f32 %0, %1;" : "=f"(y) : "f"(x)); return y;
}

// ---------------- convert fp32 x -> fp16 (hi only) ----------------
__global__ __launch_bounds__(256) void conv_x(const float* __restrict__ s,
                                              hlf* __restrict__ h, int n4) {
    int idx = blockIdx.x * 256 + threadIdx.x;
    if (idx >= n4) return;
    float4 v = ((const float4*)s)[idx];
    ((uint32_t*)h)[idx*2]   = pk2(v.x, v.y);
    ((uint32_t*)h)[idx*2+1] = pk2(v.z, v.w);
}

// ---------------- transpose + convert weights ----------------
__global__ __launch_bounds__(256) void convert_w(
    const float* __restrict__ wq, const float* __restrict__ wk,
    const float* __restrict__ wv, const float* __restrict__ wp,
    hlf* __restrict__ wth,
    hlf* __restrict__ wpth, hlf* __restrict__ wptl) {
    int idx = blockIdx.x * 256 + threadIdx.x;
    if (idx < 3 * DDIM * EDIM) {
        int k = idx & (EDIM - 1), n = (idx >> 10) & (DDIM - 1), w = idx >> 17;
        const float* W = (w == 0) ? wq : ((w == 1) ? wk : wv);
        wth[idx] = __float2half_rn(W[(size_t)k * DDIM + n]);
    }
    if (idx < DDIM * DDIM) {
        int k = idx & 127, n = idx >> 7;
        float v = wp[(size_t)k * DDIM + n];
        hlf h = __float2half_rn(v);
        wpth[idx] = h; wptl[idx] = __float2half_rn(v - __half2float(h));
    }
}

// ---------------------------------------------------------------------------
// QKV GEMM, 1-pass fp16: C[M,128] = x[M,1024] @ W^T. blockIdx.y = plane.
// BM=64, BN=128, 256 thr (2m x 4n warps), stage 24KB x2 = 48KB.
// Output truncated to fp16 anyway, so single-pass loses nothing material.
// ---------------------------------------------------------------------------
__global__ __launch_bounds__(256, 2) void mm_qkv(
    const hlf* __restrict__ Ah, const hlf* __restrict__ Bh0,
    hlf* __restrict__ Ch0) {
    extern __shared__ char smem[];
    const uint32_t sb = su32(smem);
    const int tid = threadIdx.x, lane = tid & 31, warp = tid >> 5;
    const int wm = (warp & 1) * 32, wn = (warp >> 1) * 32;
    const int m0 = blockIdx.x * 64;
    const int w = blockIdx.y;
    const hlf* Bh = Bh0 + (size_t)w * DDIM * EDIM;
    hlf* Ch = Ch0 + (size_t)w * MTOT * DDIM;
    const float oscale = (w == 0) ? QSCALE : 1.f;

    float acc[2][4][4];
#pragma unroll
    for (int i = 0; i < 2; i++)
#pragma unroll
        for (int j = 0; j < 4; j++)
#pragma unroll
            for (int u = 0; u < 4; u++) acc[i][j][u] = 0.f;

    // stage: A 8KB | B 16KB = 24KB
    auto prefetch = [&](int k0, int st) {
        uint32_t base = sb + st * 24576;
        for (int u = tid; u < 512; u += 256) {
            int r = u >> 3, c = u & 7;
            uint32_t sw = swz((uint32_t)(r * 128 + c * 16));
            cp16(base + sw, Ah + (size_t)(m0 + r) * EDIM + k0 + c * 8);
        }
        for (int u = tid; u < 1024; u += 256) {
            int r = u >> 3, c = u & 7;
            uint32_t sw = swz((uint32_t)(r * 128 + c * 16));
            cp16(base + 8192 + sw, Bh + (size_t)r * EDIM + k0 + c * 8);
        }
        CP_COMMIT();
    };

    prefetch(0, 0);
    for (int ck = 0; ck < EDIM / 64; ck++) {
        if (ck + 1 < EDIM / 64) { prefetch((ck + 1) * 64, (ck + 1) & 1); cp_wait<1>(); }
        else cp_wait<0>();
        __syncthreads();
        const uint32_t base = sb + (ck & 1) * 24576;
#pragma unroll
        for (int ks = 0; ks < 4; ks++) {
            const int kb = ks * 16;
            uint32_t a_h[2][4];
#pragma unroll
            for (int mt = 0; mt < 2; mt++) {
                int row = wm + mt * 16 + (lane & 15);
                int colb = (kb + ((lane >> 4) * 8)) * 2;
                LDSM4(a_h[mt], base + swz((uint32_t)(row * 128 + colb)));
            }
            uint32_t b_h[2][4];
#pragma unroll
            for (int np = 0; np < 2; np++) {
                int row = wn + np * 16 + ((lane >> 4) * 8) + (lane & 7);
                int colb = (kb + (((lane >> 3) & 1) * 8)) * 2;
                LDSM4(b_h[np], base + 8192 + swz((uint32_t)(row * 128 + colb)));
            }
#pragma unroll
            for (int mt = 0; mt < 2; mt++)
#pragma unroll
                for (int np = 0; np < 2; np++) {
                    MMA16816(acc[mt][np*2],   a_h[mt], b_h[np][0], b_h[np][1]);
                    MMA16816(acc[mt][np*2+1], a_h[mt], b_h[np][2], b_h[np][3]);
                }
        }
        __syncthreads();
    }

#pragma unroll
    for (int mt = 0; mt < 2; mt++)
#pragma unroll
        for (int j = 0; j < 4; j++) {
            int row = m0 + wm + mt * 16 + (lane >> 2);
            int col = wn + j * 8 + (lane & 3) * 2;
            float v0 = acc[mt][j][0] * oscale, v1 = acc[mt][j][1] * oscale;
            float v2 = acc[mt][j][2] * oscale, v3 = acc[mt][j][3] * oscale;
            *(uint32_t*)(Ch + (size_t)row * 128 + col) = pk2(v0, v1);
            *(uint32_t*)(Ch + (size_t)(row + 8) * 128 + col) = pk2(v2, v3);
        }
}

// ---------------------------------------------------------------------------
// Output projection: out[M,128] = O[M,128] @ Wp. fp16 split 3-pass, fp32 out.
// BM=64, BN=128, stage 48KB x2 = 96KB (A hi/lo + B hi/lo).
// ---------------------------------------------------------------------------
__global__ __launch_bounds__(256, 2) void mm_out(
    const hlf* __restrict__ Ah, const hlf* __restrict__ Al,
    const hlf* __restrict__ Bh, const hlf* __restrict__ Bl,
    float* __restrict__ C) {
    extern __shared__ char smem[];
    const uint32_t sb = su32(smem);
    const int tid = threadIdx.x, lane = tid & 31, warp = tid >> 5;
    const int wm = (warp & 1) * 32, wn = (warp >> 1) * 32;
    const int m0 = blockIdx.x * 64;
    const int K = DDIM;

    float acc[2][4][4];
#pragma unroll
    for (int i = 0; i < 2; i++)
#pragma unroll
        for (int j = 0; j < 4; j++)
#pragma unroll
            for (int u = 0; u < 4; u++) acc[i][j][u] = 0.f;

    auto prefetch = [&](int k0, int st) {
        uint32_t base = sb + st * 49152;
        for (int u = tid; u < 512; u += 256) {
            int r = u >> 3, c = u & 7;
            uint32_t sw = swz((uint32_t)(r * 128 + c * 16));
            size_t ao = (size_t)(m0 + r) * K + k0 + c * 8;
            cp16(base + sw, Ah + ao);
            cp16(base + 8192 + sw, Al + ao);
        }
        for (int u = tid; u < 1024; u += 256) {
            int r = u >> 3, c = u & 7;
            uint32_t sw = swz((uint32_t)(r * 128 + c * 16));
            size_t bo = (size_t)r * K + k0 + c * 8;
            cp16(base + 16384 + sw, Bh + bo);
            cp16(base + 32768 + sw, Bl + bo);
        }
        CP_COMMIT();
    };

    prefetch(0, 0);
    for (int ck = 0; ck < K / 64; ck++) {
        if (ck + 1 < K / 64) { prefetch((ck + 1) * 64, (ck + 1) & 1); cp_wait<1>(); }
        else cp_wait<0>();
        __syncthreads();
        const uint32_t base = sb + (ck & 1) * 49152;
#pragma unroll
        for (int ks = 0; ks < 4; ks++) {
            const int kb = ks * 16;
            uint32_t a_h[2][4], a_l[2][4];
#pragma unroll
            for (int mt = 0; mt < 2; mt++) {
                int row = wm + mt * 16 + (lane & 15);
                int colb = (kb + ((lane >> 4) * 8)) * 2;
                uint32_t sw = swz((uint32_t)(row * 128 + colb));
                LDSM4(a_h[mt], base + sw);
                LDSM4(a_l[mt], base + 8192 + sw);
            }
            uint32_t b_h[2][4], b_l[2][4];
#pragma unroll
            for (int np = 0; np < 2; np++) {
                int row = wn + np * 16 + ((lane >> 4) * 8) + (lane & 7);
                int colb = (kb + (((lane >> 3) & 1) * 8)) * 2;
                uint32_t sw = swz((uint32_t)(row * 128 + colb));
                LDSM4(b_h[np], base + 16384 + sw);
                LDSM4(b_l[np], base + 32768 + sw);
            }
#pragma unroll
            for (int mt = 0; mt < 2; mt++)
#pragma unroll
                for (int np = 0; np < 2; np++) {
                    MMA16816(acc[mt][np*2],   a_h[mt], b_h[np][0], b_h[np][1]);
                    MMA16816(acc[mt][np*2],   a_l[mt], b_h[np][0], b_h[np][1]);
                    MMA16816(acc[mt][np*2],   a_h[mt], b_l[np][0], b_l[np][1]);
                    MMA16816(acc[mt][np*2+1], a_h[mt], b_h[np][2], b_h[np][3]);
                    MMA16816(acc[mt][np*2+1], a_l[mt], b_h[np][2], b_h[np][3]);
                    MMA16816(acc[mt][np*2+1], a_h[mt], b_l[np][2], b_l[np][3]);
                }
        }
        __syncthreads();
    }

#pragma unroll
    for (int mt = 0; mt < 2; mt++)
#pragma unroll
        for (int j = 0; j < 4; j++) {
            int row = m0 + wm + mt * 16 + (lane >> 2);
            int col = wn + j * 8 + (lane & 3) * 2;
            *(float2*)(C + (size_t)row * 128 + col) =
                make_float2(acc[mt][j][0], acc[mt][j][1]);
            *(float2*)(C + (size_t)(row + 8) * 128 + col) =
                make_float2(acc[mt][j][2], acc[mt][j][3]);
        }
}

// ---------------------------------------------------------------------------
// Flash attention, mma.sync fp16, single-pass QK and PV. Q in registers;
// K and V both double-buffered, joint prefetch 1 tile ahead.
// smem: K0 16K | K1 16K | V0 16K | V1 16K = 64KB. 2 CTAs/SM.
// ---------------------------------------------------------------------------
__global__ __launch_bounds__(128, 2) void flash_mma(
    const hlf* __restrict__ qh, const hlf* __restrict__ kh,
    const hlf* __restrict__ vh,
    hlf* __restrict__ oh, hlf* __restrict__ ol) {
    extern __shared__ char smem[];
    const uint32_t sb = su32(smem);
    const uint32_t oK0 = 0, oK1 = 16384, oV0 = 32768, oV1 = 49152;
    const int tid = threadIdx.x, lane = tid & 31, warp = tid >> 5;
    const int wm = warp * 16;
    const int gr = lane >> 2, j2 = (lane & 3) * 2;

    // pair-balanced mapping: bid & bid+148 co-reside; weights sum ~const
    const int bid = blockIdx.x;
    const int j = (bid < 148) ? bid : (403 - bid);
    const int mt = 63 - (j >> 2), b = j & 3;
    const int m0 = mt * 64, ntiles = mt + 1;
    const size_t boff = (size_t)b * TLEN * DDIM;
    const hlf *Qh = qh + boff, *Kh = kh + boff, *Vh = vh + boff;

    auto loadKV = [&](int n0, int st) {   // 16KB K + 16KB V, one group
        uint32_t kd = sb + (st ? oK1 : oK0), vd = sb + (st ? oV1 : oV0);
        for (int u = tid; u < 1024; u += 128) {
            int rr = u >> 4, cc = u & 15;
            uint32_t sw = sw256(rr, cc * 16);
            size_t src = (size_t)(n0 + rr) * 128 + cc * 8;
            cp16(kd + sw, Kh + src);
            cp16(vd + sw, Vh + src);
        }
        CP_COMMIT();
    };

    // stage Q into V1 buffer, then prefetch K0/V0
    for (int u = tid; u < 1024; u += 128) {
        int rr = u >> 4, cc = u & 15;
        cp16(sb + oV1 + sw256(rr, cc * 16), Qh + (size_t)(m0 + rr) * 128 + cc * 8);
    }
    CP_COMMIT();
    loadKV(0, 0);
    cp_wait<1>();          // Q staged (K0/V0 may be in flight)
    __syncthreads();

    // Q fragments to registers: 8 k-steps x 4 regs
    uint32_t qa[8][4];
#pragma unroll
    for (int ks = 0; ks < 8; ks++) {
        int row = wm + (lane & 15);
        int cb = ks * 32 + ((lane >> 4) << 4);
        LDSM4(qa[ks], sb + oV1 + sw256(row, cb));
    }

    float o[16][4];
#pragma unroll
    for (int i = 0; i < 16; i++)
#pragma unroll
        for (int u = 0; u < 4; u++) o[i][u] = 0.f;
    float rm[2] = {-INFINITY, -INFINITY}, rl[2] = {0.f, 0.f};

    for (int nt = 0; nt < ntiles; nt++) {
        cp_wait<0>();           // K_nt/V_nt ready
        __syncthreads();        // all warps done reading prev buffers / Q-stage

        if (nt + 1 < ntiles) loadKV((nt + 1) * 64, (nt + 1) & 1);

        const uint32_t kbuf = sb + ((nt & 1) ? oK1 : oK0);
        const uint32_t vbuf = sb + ((nt & 1) ? oV1 : oV0);

        // ---- S = Q K^T (1-pass fp16) ----
        float s[8][4];
#pragma unroll
        for (int i = 0; i < 8; i++)
#pragma unroll
            for (int u = 0; u < 4; u++) s[i][u] = 0.f;
#pragma unroll
        for (int ks = 0; ks < 8; ks++) {
#pragma unroll
            for (int pr = 0; pr < 4; pr++) {
                uint32_t kb_h[4];
                int row = pr * 16 + ((lane >> 4) << 3) + (lane & 7);
                int cb = ks * 32 + (((lane >> 3) & 1) << 4);
                LDSM4(kb_h, kbuf + sw256(row, cb));
                MMA16816(s[pr*2],   qa[ks], kb_h[0], kb_h[1]);
                MMA16816(s[pr*2+1], qa[ks], kb_h[2], kb_h[3]);
            }
        }

        // ---- causal mask on diagonal tile ----
        if (nt == ntiles - 1) {
#pragma unroll
            for (int nt8 = 0; nt8 < 8; nt8++) {
#pragma unroll
                for (int c = 0; c < 4; c++) {
                    int col = nt8 * 8 + j2 + (c & 1);
                    int row = wm + gr + ((c >> 1) << 3);
                    if (col > row) s[nt8][c] = -1e30f;
                }
            }
        }

        // ---- online softmax ----
        float mx0 = -INFINITY, mx1 = -INFINITY;
#pragma unroll
        for (int i = 0; i < 8; i++) {
            mx0 = fmaxf(mx0, fmaxf(s[i][0], s[i][1]));
            mx1 = fmaxf(mx1, fmaxf(s[i][2], s[i][3]));
        }
        mx0 = fmaxf(mx0, __shfl_xor_sync(0xffffffffu, mx0, 1));
        mx0 = fmaxf(mx0, __shfl_xor_sync(0xffffffffu, mx0, 2));
        mx1 = fmaxf(mx1, __shfl_xor_sync(0xffffffffu, mx1, 1));
        mx1 = fmaxf(mx1, __shfl_xor_sync(0xffffffffu, mx1, 2));
        float mn0 = fmaxf(rm[0], mx0), mn1 = fmaxf(rm[1], mx1);
        float sc0 = ex2(rm[0] - mn0), sc1 = ex2(rm[1] - mn1);
        float sum0 = 0.f, sum1 = 0.f;
#pragma unroll
        for (int i = 0; i < 8; i++) {
            s[i][0] = ex2(s[i][0] - mn0); sum0 += s[i][0];
            s[i][1] = ex2(s[i][1] - mn0); sum0 += s[i][1];
            s[i][2] = ex2(s[i][2] - mn1); sum1 += s[i][2];
            s[i][3] = ex2(s[i][3] - mn1); sum1 += s[i][3];
        }
        sum0 += __shfl_xor_sync(0xffffffffu, sum0, 1);
        sum0 += __shfl_xor_sync(0xffffffffu, sum0, 2);
        sum1 += __shfl_xor_sync(0xffffffffu, sum1, 1);
        sum1 += __shfl_xor_sync(0xffffffffu, sum1, 2);
        rl[0] = rl[0] * sc0 + sum0; rl[1] = rl[1] * sc1 + sum1;
        rm[0] = mn0; rm[1] = mn1;
#pragma unroll
        for (int i = 0; i < 16; i++) {
            o[i][0] *= sc0; o[i][1] *= sc0; o[i][2] *= sc1; o[i][3] *= sc1;
        }

        // ---- pack P to fp16 (A-fragment layout) ----
        uint32_t ph[8][2];
#pragma unroll
        for (int i = 0; i < 8; i++) {
            ph[i][0] = pk2(s[i][0], s[i][1]);
            ph[i][1] = pk2(s[i][2], s[i][3]);
        }

        // ---- O += P V (1-pass fp16) ----
#pragma unroll
        for (int kk = 0; kk < 4; kk++) {
            uint32_t pa[4] = {ph[kk*2][0], ph[kk*2][1], ph[kk*2+1][0], ph[kk*2+1][1]};
#pragma unroll
            for (int dt = 0; dt < 8; dt++) {
                uint32_t vf[4];
                int row = kk * 16 + (lane & 7) + (((lane >> 3) & 1) << 3);
                int cb = dt * 32 + ((lane >> 4) << 4);
                LDSM4T(vf, vbuf + sw256(row, cb));
                MMA16816(o[dt*2],   pa, vf[0], vf[1]);
                MMA16816(o[dt*2+1], pa, vf[2], vf[3]);
            }
        }
    }

    // ---- epilogue: normalize, split to fp16 hi/lo ----
    float inv0 = 1.f / rl[0], inv1 = 1.f / rl[1];
    size_t row0 = (size_t)b * TLEN + m0 + wm + gr;
#pragma unroll
    for (int dt = 0; dt < 16; dt++) {
        int col = dt * 8 + j2;
        float v0 = o[dt][0] * inv0, v1 = o[dt][1] * inv0;
        float v2 = o[dt][2] * inv1, v3 = o[dt][3] * inv1;
        uint32_t h0 = pk2(v0, v1), h1 = pk2(v2, v3);
        *(uint32_t*)(oh + row0 * 128 + col) = h0;
        *(uint32_t*)(ol + row0 * 128 + col) = pk2(v0 - lo_f(h0), v1 - hi_f(h0));
        *(uint32_t*)(oh + (row0 + 8) * 128 + col) = h1;
        *(uint32_t*)(ol + (row0 + 8) * 128 + col) = pk2(v2 - lo_f(h1), v3 - hi_f(h1));
    }
}

// ---------------------------------------------------------------------------
extern "C" void kernel_launch(void* const* d_in, const int* in_sizes, int n_in,
                              void* d_out, int out_size) {
    const float* x  = (const float*)d_in[0];
    const float* Wk = (const float*)d_in[1];
    const float* Wq = (const float*)d_in[2];
    const float* Wv = (const float*)d_in[3];
    const float* Wp = (const float*)d_in[4];
    float* out = (float*)d_out;

    hlf *xh, *wth, *wpth, *wptl, *qkvh, *oh, *ol;
    cudaGetSymbolAddress((void**)&xh, g_xh);
    cudaGetSymbolAddress((void**)&wth, g_wth);
    cudaGetSymbolAddress((void**)&wpth, g_wpth); cudaGetSymbolAddress((void**)&wptl, g_wptl);
    cudaGetSymbolAddress((void**)&qkvh, g_qkvh);
    cudaGetSymbolAddress((void**)&oh, g_oh);     cudaGetSymbolAddress((void**)&ol, g_ol);

    const int qkv_smem = 49152;   // 2 stages x 24KB
    const int out_smem = 98304;   // 2 stages x 48KB
    const int fa_smem  = 65536;   // K0 + K1 + V0 + V1
    cudaFuncSetAttribute(mm_qkv, cudaFuncAttributeMaxDynamicSharedMemorySize, qkv_smem);
    cudaFuncSetAttribute(mm_out, cudaFuncAttributeMaxDynamicSharedMemorySize, out_smem);
    cudaFuncSetAttribute(flash_mma, cudaFuncAttributeMaxDynamicSharedMemorySize, fa_smem);

    conv_x<<<MTOT * EDIM / 4 / 256, 256>>>(x, xh, MTOT * EDIM / 4);
    convert_w<<<(3 * DDIM * EDIM + 255) / 256, 256>>>(Wq, Wk, Wv, Wp, wth, wpth, wptl);

    // fused QKV (1-pass): blockIdx.y = plane (0:q with QSCALE, 1:k, 2:v)
    mm_qkv<<<dim3(MTOT / 64, 3), 256, qkv_smem>>>(xh, wth, qkvh);

    const size_t P = (size_t)MTOT * DDIM;
    flash_mma<<<256, 128, fa_smem>>>(qkvh, qkvh + P, qkvh + 2 * P, oh, ol);

    mm_out<<<MTOT / 64, 256, out_smem>>>(oh, ol, wpth, wptl, out);
}